// round 14
// baseline (speedup 1.0000x reference)
#include <cuda_runtime.h>
#include <cuda_bf16.h>
#include <math.h>
#include <stdint.h>

#define S_LEN 2048
#define DM 1024
#define NHEADS 16
#define DH 64
#define DFF 4096
#define NROWS 4096   // B*S = 2*2048
#define WINDOW 512

#define BP 40        // bf16 smem pitch for GEMM tiles (80B rows)
#define AP 72        // bf16 smem pitch for attention tiles (144B rows)

// ---------------- scratch (static device globals; no allocation) ----------------
__device__ float g_q[NROWS * DM];
__device__ float g_k[NROWS * DM];
__device__ float g_v[NROWS * DM];
__device__ float g_h[NROWS * DM];
__device__ float g_ct[S_LEN * 32], g_st[S_LEN * 32];           // rope tables
__device__ __nv_bfloat16 g_xh[NROWS * DM], g_xl[NROWS * DM];   // LN1 out (split)
__device__ __nv_bfloat16 g_ch[NROWS * DM], g_cl[NROWS * DM];   // ctx (split)
__device__ __nv_bfloat16 g_yh[NROWS * DM], g_yl[NROWS * DM];   // LN2 out (split)
__device__ __nv_bfloat16 g_mh[NROWS * DFF], g_ml[NROWS * DFF]; // mid (split)
__device__ __nv_bfloat16 g_wth[DM * DFF], g_wtl[DM * DFF];     // weight^T (split)
__device__ __nv_bfloat16 g_qh[NROWS * DM], g_ql[NROWS * DM];   // q split (rotated)
__device__ __nv_bfloat16 g_kh[NROWS * DM], g_kl[NROWS * DM];   // k split (rotated)
__device__ __nv_bfloat16 g_vh[NROWS * DM];                     // v hi only

// =================== helpers ===================
__device__ __forceinline__ uint32_t cvta_shared_u32(const void* p) {
    uint32_t a;
    asm("{ .reg .u64 t; cvta.to.shared.u64 t, %1; cvt.u32.u64 %0, t; }"
        : "=r"(a) : "l"(p));
    return a;
}
__device__ __forceinline__ void ldm_x4(uint32_t addr, uint32_t* r) {
    asm volatile("ldmatrix.sync.aligned.m8n8.x4.shared.b16 {%0,%1,%2,%3}, [%4];"
                 : "=r"(r[0]), "=r"(r[1]), "=r"(r[2]), "=r"(r[3]) : "r"(addr));
}
__device__ __forceinline__ void ldm_x4_t(uint32_t addr, uint32_t* r) {
    asm volatile("ldmatrix.sync.aligned.m8n8.x4.trans.shared.b16 {%0,%1,%2,%3}, [%4];"
                 : "=r"(r[0]), "=r"(r[1]), "=r"(r[2]), "=r"(r[3]) : "r"(addr));
}
__device__ __forceinline__ void mma_bf16(float* c, const uint32_t* a,
                                         uint32_t b0, uint32_t b1) {
    asm volatile(
        "mma.sync.aligned.m16n8k16.row.col.f32.bf16.bf16.f32 "
        "{%0,%1,%2,%3}, {%4,%5,%6,%7}, {%8,%9}, {%0,%1,%2,%3};"
        : "+f"(c[0]), "+f"(c[1]), "+f"(c[2]), "+f"(c[3])
        : "r"(a[0]), "r"(a[1]), "r"(a[2]), "r"(a[3]), "r"(b0), "r"(b1));
}
__device__ __forceinline__ void split_bf16(float x, __nv_bfloat16& h, __nv_bfloat16& l) {
    h = __float2bfloat16(x);
    l = __float2bfloat16(x - __bfloat162float(h));
}
__device__ __forceinline__ uint2 pack4(__nv_bfloat16 a, __nv_bfloat16 b,
                                       __nv_bfloat16 c, __nv_bfloat16 d) {
    __nv_bfloat162 p0 = __halves2bfloat162(a, b);
    __nv_bfloat162 p1 = __halves2bfloat162(c, d);
    uint2 r;
    r.x = *(uint32_t*)&p0;
    r.y = *(uint32_t*)&p1;
    return r;
}
__device__ __forceinline__ uint32_t pack2f(float a, float b) {
    __nv_bfloat162 p = __floats2bfloat162_rn(a, b);
    return *(uint32_t*)&p;
}
__device__ __forceinline__ void cp16(uint32_t saddr, const void* g) {
    asm volatile("cp.async.cg.shared.global [%0], [%1], 16;"
                 :: "r"(saddr), "l"(g));
}
__device__ __forceinline__ float rebf(__nv_bfloat16 h, __nv_bfloat16 l) {
    return __bfloat162float(h) + __bfloat162float(l);
}

// =================== weight transpose + split: W[K,N] -> Wt[N,K] hi/lo ==========
__global__ void wsplit_t(const float* __restrict__ W,
                         __nv_bfloat16* __restrict__ Th,
                         __nv_bfloat16* __restrict__ Tl, int K, int N)
{
    __shared__ float t[32][33];
    int nb = blockIdx.x * 32, kb = blockIdx.y * 32;
    int tx = threadIdx.x, ty = threadIdx.y;
    #pragma unroll
    for (int r = 0; r < 4; r++)
        t[ty + r * 8][tx] = W[(size_t)(kb + ty + r * 8) * N + nb + tx];
    __syncthreads();
    #pragma unroll
    for (int r = 0; r < 4; r++) {
        int n = nb + ty + r * 8;
        float x = t[tx][ty + r * 8];
        __nv_bfloat16 hh, ll;
        split_bf16(x, hh, ll);
        Th[(size_t)n * K + kb + tx] = hh;
        Tl[(size_t)n * K + kb + tx] = ll;
    }
}

// =================== bf16x3 mma.sync GEMM v3 (R9-proven) ===================
template<bool GELU, bool SPLIT_OUT>
__global__ void __launch_bounds__(128, 2)
gemm_v3(const __nv_bfloat16* __restrict__ Ah, const __nv_bfloat16* __restrict__ Al,
        const __nv_bfloat16* __restrict__ Bth, const __nv_bfloat16* __restrict__ Btl,
        const float* __restrict__ bias, const float* __restrict__ residual,
        float* __restrict__ C, __nv_bfloat16* __restrict__ Ch,
        __nv_bfloat16* __restrict__ Cl, int M, int N, int K)
{
    extern __shared__ __nv_bfloat16 S[];
    uint32_t smem_u = cvta_shared_u32(S);

    int tid = threadIdx.x, wid = tid >> 5, lane = tid & 31;
    int g = lane >> 2, tg = lane & 3;
    int warpM = wid >> 1, warpN = wid & 1;
    int bm = blockIdx.y * 128, bn = blockIdx.x * 128;
    const int NS = K >> 5;

    float acc[4][8][4];
    #pragma unroll
    for (int mi = 0; mi < 4; mi++)
        #pragma unroll
        for (int ni = 0; ni < 8; ni++)
            #pragma unroll
            for (int r = 0; r < 4; r++) acc[mi][ni][r] = 0.0f;

    auto issue_stage = [&](int s, int b) {
        int k0 = s << 5;
        uint32_t sb = smem_u + b * 40960;
        #pragma unroll
        for (int u = 0; u < 4; u++) {
            int idx = (u << 7) + tid;
            int r = idx >> 2, c = idx & 3;
            uint32_t soff = (uint32_t)(r * BP + (c << 3)) * 2;
            size_t ga = (size_t)(bm + r) * K + k0 + (c << 3);
            size_t gb = (size_t)(bn + r) * K + k0 + (c << 3);
            cp16(sb + soff,         Ah + ga);
            cp16(sb + 10240 + soff, Al + ga);
            cp16(sb + 20480 + soff, Bth + gb);
            cp16(sb + 30720 + soff, Btl + gb);
        }
    };

    issue_stage(0, 0);
    asm volatile("cp.async.commit_group;" ::: "memory");

    int l8 = lane & 7, qq = lane >> 3;
    int brow_base = warpN * 64 + ((qq >> 1) << 3) + l8;
    int bcol_base = (qq & 1) << 3;

    for (int s = 0; s < NS; s++) {
        int b = s & 1;
        if (s + 1 < NS) {
            issue_stage(s + 1, b ^ 1);
            asm volatile("cp.async.commit_group;" ::: "memory");
            asm volatile("cp.async.wait_group 1;" ::: "memory");
        } else {
            asm volatile("cp.async.wait_group 0;" ::: "memory");
        }
        __syncthreads();

        uint32_t baseA = smem_u + b * 40960;
        uint32_t baseB = baseA + 20480;

        #pragma unroll
        for (int ks = 0; ks < 2; ks++) {
            uint32_t ah[4][4], al[4][4];
            int rowsel = lane & 15;
            int colsel = (ks << 4) + ((lane >> 4) << 3);
            #pragma unroll
            for (int mi = 0; mi < 4; mi++) {
                int row = (warpM << 6) + (mi << 4) + rowsel;
                uint32_t ad = baseA + (uint32_t)(row * BP + colsel) * 2;
                ldm_x4(ad, ah[mi]);
                ldm_x4(ad + 10240, al[mi]);
            }
            uint32_t bh[8][2], bl[8][2];
            #pragma unroll
            for (int pr = 0; pr < 4; pr++) {
                int row = brow_base + (pr << 4);
                uint32_t ba = baseB + (uint32_t)(row * BP + bcol_base + (ks << 4)) * 2;
                uint32_t t[4];
                ldm_x4(ba, t);
                bh[2*pr][0] = t[0]; bh[2*pr][1] = t[1];
                bh[2*pr+1][0] = t[2]; bh[2*pr+1][1] = t[3];
                ldm_x4(ba + 10240, t);
                bl[2*pr][0] = t[0]; bl[2*pr][1] = t[1];
                bl[2*pr+1][0] = t[2]; bl[2*pr+1][1] = t[3];
            }
            #pragma unroll
            for (int ni = 0; ni < 8; ni++)
                #pragma unroll
                for (int mi = 0; mi < 4; mi++) {
                    mma_bf16(acc[mi][ni], ah[mi], bh[ni][0], bh[ni][1]);
                    mma_bf16(acc[mi][ni], ah[mi], bl[ni][0], bl[ni][1]);
                    mma_bf16(acc[mi][ni], al[mi], bh[ni][0], bh[ni][1]);
                }
        }
        __syncthreads();
    }

    // ---- epilogue ----
    #pragma unroll
    for (int mi = 0; mi < 4; mi++) {
        int r0 = bm + (warpM << 6) + (mi << 4) + g;
        #pragma unroll
        for (int ni = 0; ni < 8; ni++) {
            int c = bn + (warpN << 6) + (ni << 3) + (tg << 1);
            float b0 = bias[c], b1 = bias[c + 1];
            float v00 = acc[mi][ni][0] + b0;
            float v01 = acc[mi][ni][1] + b1;
            float v10 = acc[mi][ni][2] + b0;
            float v11 = acc[mi][ni][3] + b1;
            if (residual) {
                float2 r0v = *(const float2*)&residual[(size_t)r0 * N + c];
                float2 r1v = *(const float2*)&residual[(size_t)(r0 + 8) * N + c];
                v00 += r0v.x; v01 += r0v.y; v10 += r1v.x; v11 += r1v.y;
            }
            if (GELU) {
                v00 = 0.5f * v00 * (1.0f + erff(v00 * 0.70710678118654752f));
                v01 = 0.5f * v01 * (1.0f + erff(v01 * 0.70710678118654752f));
                v10 = 0.5f * v10 * (1.0f + erff(v10 * 0.70710678118654752f));
                v11 = 0.5f * v11 * (1.0f + erff(v11 * 0.70710678118654752f));
            }
            if (SPLIT_OUT) {
                __nv_bfloat16 h0, l0, h1, l1;
                split_bf16(v00, h0, l0); split_bf16(v01, h1, l1);
                *(__nv_bfloat162*)&Ch[(size_t)r0 * N + c] = __halves2bfloat162(h0, h1);
                *(__nv_bfloat162*)&Cl[(size_t)r0 * N + c] = __halves2bfloat162(l0, l1);
                split_bf16(v10, h0, l0); split_bf16(v11, h1, l1);
                *(__nv_bfloat162*)&Ch[(size_t)(r0 + 8) * N + c] = __halves2bfloat162(h0, h1);
                *(__nv_bfloat162*)&Cl[(size_t)(r0 + 8) * N + c] = __halves2bfloat162(l0, l1);
            } else {
                float2 w0 = {v00, v01}, w1 = {v10, v11};
                *(float2*)&C[(size_t)r0 * N + c] = w0;
                *(float2*)&C[(size_t)(r0 + 8) * N + c] = w1;
            }
        }
    }
}

#define GEMM_SMEM_BYTES 81920

// ---------------- LayerNorm -> split bf16 out ----------------
__global__ void ln_kernel(const float* __restrict__ x, const float* __restrict__ g,
                          const float* __restrict__ b,
                          __nv_bfloat16* __restrict__ yh, __nv_bfloat16* __restrict__ yl)
{
    int row = blockIdx.x;
    int tid = threadIdx.x;
    const float4* xr = (const float4*)(x + (size_t)row * DM);
    float4 v = xr[tid];

    __shared__ float rs[256];
    rs[tid] = v.x + v.y + v.z + v.w;
    __syncthreads();
    for (int k = 128; k > 0; k >>= 1) {
        if (tid < k) rs[tid] += rs[tid + k];
        __syncthreads();
    }
    float mean = rs[0] * (1.0f / DM);
    __syncthreads();

    float dx0 = v.x - mean, dx1 = v.y - mean, dx2 = v.z - mean, dx3 = v.w - mean;
    rs[tid] = dx0*dx0 + dx1*dx1 + dx2*dx2 + dx3*dx3;
    __syncthreads();
    for (int k = 128; k > 0; k >>= 1) {
        if (tid < k) rs[tid] += rs[tid + k];
        __syncthreads();
    }
    float var = rs[0] * (1.0f / DM);
    float inv = rsqrtf(var + 1e-5f);

    float4 gg = ((const float4*)g)[tid];
    float4 bb = ((const float4*)b)[tid];
    float o0 = dx0 * inv * gg.x + bb.x;
    float o1 = dx1 * inv * gg.y + bb.y;
    float o2 = dx2 * inv * gg.z + bb.z;
    float o3 = dx3 * inv * gg.w + bb.w;
    __nv_bfloat16 h0, l0, h1, l1, h2, l2, h3, l3;
    split_bf16(o0, h0, l0); split_bf16(o1, h1, l1);
    split_bf16(o2, h2, l2); split_bf16(o3, h3, l3);
    size_t off = (size_t)row * DM + tid * 4;
    *(uint2*)&yh[off] = pack4(h0, h1, h2, h3);
    *(uint2*)&yl[off] = pack4(l0, l1, l2, l3);
}

// ---------------- rope cos/sin tables (same math as reference rope) ----------
__global__ void rope_table(float* __restrict__ ct, float* __restrict__ st)
{
    int t = blockIdx.x * 256 + threadIdx.x;   // S_LEN*32 threads
    if (t >= S_LEN * 32) return;
    int s = t >> 5, i = t & 31;
    float invf = 1.0f / powf(10000.0f, (float)(2 * i) / 64.0f);
    float ang = (float)s * invf;
    ct[t] = cosf(ang);
    st[t] = sinf(ang);
}

// ---------------- fused rope + split (table-driven, zero MUFU) ----------------
// q,k,v fp32 stay unrotated in gmem; rotation applied in fp32 before splitting
// (bit-identical to rope-then-split). v: hi only.
__global__ void qkv_rope_split(const float* __restrict__ q, const float* __restrict__ k,
                               const float* __restrict__ v,
                               const float* __restrict__ ct, const float* __restrict__ st,
                               __nv_bfloat16* __restrict__ qh, __nv_bfloat16* __restrict__ ql,
                               __nv_bfloat16* __restrict__ kh, __nv_bfloat16* __restrict__ kl,
                               __nv_bfloat16* __restrict__ vh)
{
    size_t t = (size_t)blockIdx.x * 256 + threadIdx.x;   // NROWS*DM/4 threads
    size_t off = t * 4;
    int d = (int)(off & (DM - 1));
    int n = (int)(off >> 10);
    int s = n & (S_LEN - 1);
    int i = d & 31;                     // freq index of this 4-chunk
    bool first = (d & 32) == 0;

    float4 cv = *(const float4*)&ct[s * 32 + i];
    float4 sv = *(const float4*)&st[s * 32 + i];
    float cs[4] = {cv.x, cv.y, cv.z, cv.w};
    float ss[4] = {sv.x, sv.y, sv.z, sv.w};

    __nv_bfloat16 h0, l0, h1, l1, h2, l2, h3, l3;

    // ---- q ----
    {
        float4 a = *(const float4*)&q[off];
        float4 p = first ? *(const float4*)&q[off + 32]
                         : *(const float4*)&q[off - 32];
        float xs[4] = {a.x, a.y, a.z, a.w};
        float ps[4] = {p.x, p.y, p.z, p.w};
        #pragma unroll
        for (int r = 0; r < 4; r++)
            xs[r] = first ? (xs[r] * cs[r] - ps[r] * ss[r])
                          : (xs[r] * cs[r] + ps[r] * ss[r]);
        split_bf16(xs[0], h0, l0); split_bf16(xs[1], h1, l1);
        split_bf16(xs[2], h2, l2); split_bf16(xs[3], h3, l3);
        *(uint2*)&qh[off] = pack4(h0, h1, h2, h3);
        *(uint2*)&ql[off] = pack4(l0, l1, l2, l3);
    }
    // ---- k ----
    {
        float4 a = *(const float4*)&k[off];
        float4 p = first ? *(const float4*)&k[off + 32]
                         : *(const float4*)&k[off - 32];
        float xs[4] = {a.x, a.y, a.z, a.w};
        float ps[4] = {p.x, p.y, p.z, p.w};
        #pragma unroll
        for (int r = 0; r < 4; r++)
            xs[r] = first ? (xs[r] * cs[r] - ps[r] * ss[r])
                          : (xs[r] * cs[r] + ps[r] * ss[r]);
        split_bf16(xs[0], h0, l0); split_bf16(xs[1], h1, l1);
        split_bf16(xs[2], h2, l2); split_bf16(xs[3], h3, l3);
        *(uint2*)&kh[off] = pack4(h0, h1, h2, h3);
        *(uint2*)&kl[off] = pack4(l0, l1, l2, l3);
    }
    // ---- v (hi only) ----
    {
        float4 a = *(const float4*)&v[off];
        *(uint2*)&vh[off] = pack4(__float2bfloat16(a.x), __float2bfloat16(a.y),
                                  __float2bfloat16(a.z), __float2bfloat16(a.w));
    }
}

// ================= FlashAttention-2 style mma attention (V hi-only) =============
#define ATT_SMEM (5 * 64 * AP * 2)

__global__ void __launch_bounds__(128)
attn_mma(const __nv_bfloat16* __restrict__ qh_g, const __nv_bfloat16* __restrict__ ql_g,
         const __nv_bfloat16* __restrict__ kh_g, const __nv_bfloat16* __restrict__ kl_g,
         const __nv_bfloat16* __restrict__ vh_g,
         __nv_bfloat16* __restrict__ ch, __nv_bfloat16* __restrict__ cl,
         const int* __restrict__ gidx)
{
    extern __shared__ __nv_bfloat16 AS[];
    __nv_bfloat16* Qh = AS;
    __nv_bfloat16* Ql = Qh + 64 * AP;
    __nv_bfloat16* Kh = Ql + 64 * AP;
    __nv_bfloat16* Kl = Kh + 64 * AP;
    __nv_bfloat16* Vh = Kl + 64 * AP;
    __shared__ unsigned char gflag[64];
    __shared__ int glist[8];
    __shared__ int ng_s;

    int q0 = blockIdx.x * 64, h = blockIdx.y, b = blockIdx.z;
    int tid = threadIdx.x, wid = tid >> 5, lane = tid & 31;
    int g = lane >> 2, tg = lane & 3;

    uint32_t qh_u = cvta_shared_u32(Qh);
    uint32_t vh_u = cvta_shared_u32(Vh);

    int g0 = gidx[0], g1 = gidx[1], g2 = gidx[2], g3 = gidx[3];
    int g4 = gidx[4], g5 = gidx[5], g6 = gidx[6], g7 = gidx[7];

    size_t rowbase = ((size_t)(b * S_LEN + q0)) * DM + h * DH;
    for (int u = tid; u < 512; u += 128) {
        int r = u >> 3, c8 = (u & 7) << 3;
        size_t ga = rowbase + (size_t)r * DM + c8;
        *(uint4*)&Qh[r * AP + c8] = *(const uint4*)&qh_g[ga];
        *(uint4*)&Ql[r * AP + c8] = *(const uint4*)&ql_g[ga];
    }

    int lo = q0 - (WINDOW - 1);
    if (lo < 0) lo = 0;
    int jt_start = (lo >> 6) << 6;

    if (tid == 0) {
        int ng = 0;
        int gs[8] = {g0, g1, g2, g3, g4, g5, g6, g7};
        for (int t = 0; t < 8; t++) {
            int j = gs[t];
            if (j < jt_start) {
                bool dup = false;
                for (int u = 0; u < ng; u++) if (glist[u] == j) dup = true;
                if (!dup) glist[ng++] = j;
            }
        }
        ng_s = ng;
    }
    __syncthreads();
    int ng = ng_s;

    uint32_t aqh[4][4], aql[4][4];
    {
        int rowsel = lane & 15;
        int colsel = (lane >> 4) << 3;
        #pragma unroll
        for (int kk = 0; kk < 4; kk++) {
            uint32_t qa = qh_u + (uint32_t)(((wid << 4) + rowsel) * AP + (kk << 4) + colsel) * 2;
            ldm_x4(qa, aqh[kk]);
            ldm_x4(qa + 9216, aql[kk]);
        }
    }

    float m0 = -1e30f, l0 = 0.0f, m1 = -1e30f, l1 = 0.0f;
    float o[8][4];
    #pragma unroll
    for (int ni = 0; ni < 8; ni++)
        #pragma unroll
        for (int r = 0; r < 4; r++) o[ni][r] = 0.0f;

    int i0 = q0 + (wid << 4) + g;
    int i1 = i0 + 8;

    auto process = [&](int jt0, bool extras) {
        float sc[8][4];
        #pragma unroll
        for (int ni = 0; ni < 8; ni++)
            #pragma unroll
            for (int r = 0; r < 4; r++) sc[ni][r] = 0.0f;

        #pragma unroll
        for (int kk = 0; kk < 4; kk++) {
            int koff = (kk << 4) + (tg << 1);
            #pragma unroll
            for (int ni = 0; ni < 8; ni++) {
                int krow = (ni << 3) + g;
                uint32_t bh0 = *(const uint32_t*)&Kh[krow * AP + koff];
                uint32_t bh1 = *(const uint32_t*)&Kh[krow * AP + koff + 8];
                uint32_t bl0 = *(const uint32_t*)&Kl[krow * AP + koff];
                uint32_t bl1 = *(const uint32_t*)&Kl[krow * AP + koff + 8];
                mma_bf16(sc[ni], aqh[kk], bh0, bh1);
                mma_bf16(sc[ni], aql[kk], bh0, bh1);
                mma_bf16(sc[ni], aqh[kk], bl0, bl1);
            }
        }

        #pragma unroll
        for (int ni = 0; ni < 8; ni++) {
            #pragma unroll
            for (int cc = 0; cc < 2; cc++) {
                int jr = (ni << 3) + (tg << 1) + cc;
                bool a0, a1;
                if (extras) {
                    a0 = a1 = (jr < ng);
                } else {
                    int j = jt0 + jr;
                    bool fl = gflag[jr] != 0;
                    a0 = (j <= i0) && (((i0 - j) < WINDOW) || fl);
                    a1 = (j <= i1) && (((i1 - j) < WINDOW) || fl);
                }
                sc[ni][cc]     = a0 ? sc[ni][cc] * 0.125f     : -1e30f;
                sc[ni][2 + cc] = a1 ? sc[ni][2 + cc] * 0.125f : -1e30f;
            }
        }

        float t0 = -1e30f, t1 = -1e30f;
        #pragma unroll
        for (int ni = 0; ni < 8; ni++) {
            t0 = fmaxf(t0, fmaxf(sc[ni][0], sc[ni][1]));
            t1 = fmaxf(t1, fmaxf(sc[ni][2], sc[ni][3]));
        }
        t0 = fmaxf(t0, __shfl_xor_sync(0xffffffffu, t0, 1));
        t0 = fmaxf(t0, __shfl_xor_sync(0xffffffffu, t0, 2));
        t1 = fmaxf(t1, __shfl_xor_sync(0xffffffffu, t1, 1));
        t1 = fmaxf(t1, __shfl_xor_sync(0xffffffffu, t1, 2));
        float nm0 = fmaxf(m0, t0), nm1 = fmaxf(m1, t1);
        float esc0 = __expf(m0 - nm0), esc1 = __expf(m1 - nm1);
        float s0 = 0.0f, s1 = 0.0f;
        #pragma unroll
        for (int ni = 0; ni < 8; ni++) {
            #pragma unroll
            for (int cc = 0; cc < 2; cc++) {
                float p = __expf(sc[ni][cc] - nm0);
                p = __bfloat162float(__float2bfloat16(p));
                sc[ni][cc] = p;
                s0 += p;
                float p2 = __expf(sc[ni][2 + cc] - nm1);
                p2 = __bfloat162float(__float2bfloat16(p2));
                sc[ni][2 + cc] = p2;
                s1 += p2;
            }
        }
        s0 += __shfl_xor_sync(0xffffffffu, s0, 1);
        s0 += __shfl_xor_sync(0xffffffffu, s0, 2);
        s1 += __shfl_xor_sync(0xffffffffu, s1, 1);
        s1 += __shfl_xor_sync(0xffffffffu, s1, 2);
        l0 = l0 * esc0 + s0;
        l1 = l1 * esc1 + s1;
        m0 = nm0; m1 = nm1;
        #pragma unroll
        for (int ni = 0; ni < 8; ni++) {
            o[ni][0] *= esc0; o[ni][1] *= esc0;
            o[ni][2] *= esc1; o[ni][3] *= esc1;
        }

        int vrow = lane & 15;
        int vcol = (lane >> 4) << 3;
        #pragma unroll
        for (int kk = 0; kk < 4; kk++) {
            uint32_t ap[4];
            ap[0] = pack2f(sc[2 * kk][0], sc[2 * kk][1]);
            ap[1] = pack2f(sc[2 * kk][2], sc[2 * kk][3]);
            ap[2] = pack2f(sc[2 * kk + 1][0], sc[2 * kk + 1][1]);
            ap[3] = pack2f(sc[2 * kk + 1][2], sc[2 * kk + 1][3]);
            #pragma unroll
            for (int np = 0; np < 4; np++) {
                uint32_t va = vh_u + (uint32_t)(((kk << 4) + vrow) * AP + (np << 4) + vcol) * 2;
                uint32_t bv[4];
                ldm_x4_t(va, bv);
                mma_bf16(o[2 * np],     ap, bv[0], bv[1]);
                mma_bf16(o[2 * np + 1], ap, bv[2], bv[3]);
            }
        }
    };

    if (ng > 0) {
        for (int u = tid; u < 512; u += 128) {
            int r = u >> 3, c8 = (u & 7) << 3;
            if (r < ng) {
                size_t ga = ((size_t)(b * S_LEN + glist[r])) * DM + h * DH + c8;
                *(uint4*)&Kh[r * AP + c8] = *(const uint4*)&kh_g[ga];
                *(uint4*)&Kl[r * AP + c8] = *(const uint4*)&kl_g[ga];
                *(uint4*)&Vh[r * AP + c8] = *(const uint4*)&vh_g[ga];
            } else {
                uint4 z = {0, 0, 0, 0};
                *(uint4*)&Vh[r * AP + c8] = z;
                *(uint4*)&Kh[r * AP + c8] = z;
                *(uint4*)&Kl[r * AP + c8] = z;
            }
        }
        __syncthreads();
        process(0, true);
        __syncthreads();
    }

    for (int jt0 = jt_start; jt0 <= q0; jt0 += 64) {
        for (int u = tid; u < 512; u += 128) {
            int r = u >> 3, c8 = (u & 7) << 3;
            size_t ga = ((size_t)(b * S_LEN + jt0 + r)) * DM + h * DH + c8;
            *(uint4*)&Kh[r * AP + c8] = *(const uint4*)&kh_g[ga];
            *(uint4*)&Kl[r * AP + c8] = *(const uint4*)&kl_g[ga];
            *(uint4*)&Vh[r * AP + c8] = *(const uint4*)&vh_g[ga];
        }
        if (tid < 64) {
            int j = jt0 + tid;
            gflag[tid] = (j==g0)||(j==g1)||(j==g2)||(j==g3)||(j==g4)||(j==g5)||(j==g6)||(j==g7);
        }
        __syncthreads();
        process(jt0, false);
        __syncthreads();
    }

    float inv0 = 1.0f / l0, inv1 = 1.0f / l1;
    size_t base0 = ((size_t)(b * S_LEN + i0)) * DM + h * DH;
    size_t base1 = base0 + (size_t)8 * DM;
    #pragma unroll
    for (int ni = 0; ni < 8; ni++) {
        int c = (ni << 3) + (tg << 1);
        __nv_bfloat16 h0, lo0, h1, lo1;
        split_bf16(o[ni][0] * inv0, h0, lo0);
        split_bf16(o[ni][1] * inv0, h1, lo1);
        *(__nv_bfloat162*)&ch[base0 + c] = __halves2bfloat162(h0, h1);
        *(__nv_bfloat162*)&cl[base0 + c] = __halves2bfloat162(lo0, lo1);
        split_bf16(o[ni][2] * inv1, h0, lo0);
        split_bf16(o[ni][3] * inv1, h1, lo1);
        *(__nv_bfloat162*)&ch[base1 + c] = __halves2bfloat162(h0, h1);
        *(__nv_bfloat162*)&cl[base1 + c] = __halves2bfloat162(lo0, lo1);
    }
}

// ---------------- fix-up: exact full-causal rows for global queries ----------
// q,k from rotated split bf16 (hi+lo reconstruct); v exact fp32.
__global__ void __launch_bounds__(128)
attn_global_fix(const __nv_bfloat16* __restrict__ qh_g, const __nv_bfloat16* __restrict__ ql_g,
                const __nv_bfloat16* __restrict__ kh_g, const __nv_bfloat16* __restrict__ kl_g,
                const float* __restrict__ v,
                __nv_bfloat16* __restrict__ ch, __nv_bfloat16* __restrict__ cl,
                const int* __restrict__ gidx)
{
    int i = gidx[blockIdx.x];
    int h = blockIdx.y;
    int b = blockIdx.z;
    int tid = threadIdx.x;

    __shared__ float qs[DH];
    __shared__ float p[S_LEN];
    __shared__ float red[128];
    __shared__ float ctxp[2][DH];

    size_t qbase = ((size_t)(b * S_LEN + i)) * DM + h * DH;
    if (tid < DH) qs[tid] = rebf(qh_g[qbase + tid], ql_g[qbase + tid]);
    __syncthreads();

    int n = i + 1;

    for (int j = tid; j < n; j += 128) {
        size_t kb = ((size_t)(b * S_LEN + j)) * DM + h * DH;
        float d = 0.0f;
        #pragma unroll
        for (int dd = 0; dd < DH; dd++)
            d += qs[dd] * rebf(kh_g[kb + dd], kl_g[kb + dd]);
        p[j] = d * 0.125f;
    }
    __syncthreads();

    float mx_p = -1e30f;
    for (int j = tid; j < n; j += 128) mx_p = fmaxf(mx_p, p[j]);
    red[tid] = mx_p; __syncthreads();
    for (int s2 = 64; s2 > 0; s2 >>= 1) {
        if (tid < s2) red[tid] = fmaxf(red[tid], red[tid + s2]);
        __syncthreads();
    }
    float mx = red[0];
    __syncthreads();

    float sm = 0.0f;
    for (int j = tid; j < n; j += 128) {
        float e = __expf(p[j] - mx);
        p[j] = e;
        sm += e;
    }
    red[tid] = sm; __syncthreads();
    for (int s2 = 64; s2 > 0; s2 >>= 1) {
        if (tid < s2) red[tid] += red[tid + s2];
        __syncthreads();
    }
    float denom = red[0];

    int half = tid >> 6, d = tid & 63;
    float acc = 0.0f;
    for (int j = half; j < n; j += 2)
        acc += p[j] * v[((size_t)(b * S_LEN + j)) * DM + h * DH + d];
    ctxp[half][d] = acc;
    __syncthreads();
    if (tid < DH) {
        float val = (ctxp[0][tid] + ctxp[1][tid]) / denom;
        __nv_bfloat16 hh, ll;
        split_bf16(val, hh, ll);
        ch[qbase + tid] = hh;
        cl[qbase + tid] = ll;
    }
}

// ---------------- sentinel ----------------
__global__ void sentinel_kernel(float* out, int n)
{
    int t = blockIdx.x * blockDim.x + threadIdx.x;
    if (t < n) out[t] = 1.0e6f;
}

// ---------------- host launcher ----------------
extern "C" void kernel_launch(void* const* d_in, const int* in_sizes, int n_in,
                              void* d_out, int out_size)
{
    float* out = (float*)d_out;

    bool ok = (n_in == 18)
        && (in_sizes[0]  == NROWS * DM)
        && (in_sizes[1]  == DM)
        && (in_sizes[3]  == DM * DM)
        && (in_sizes[13] == DM * DFF)
        && (in_sizes[14] == DFF)
        && (in_sizes[15] == DFF * DM)
        && (in_sizes[16] == DM)
        && (in_sizes[17] == 8);
    if (!ok) {
        sentinel_kernel<<<(out_size + 255) / 256, 256>>>(out, out_size);
        return;
    }

    const float* hidden = (const float*)d_in[0];
    const float* ln1_g  = (const float*)d_in[1];
    const float* ln1_b  = (const float*)d_in[2];
    const float* wq     = (const float*)d_in[3];
    const float* bq     = (const float*)d_in[4];
    const float* wk     = (const float*)d_in[5];
    const float* bk     = (const float*)d_in[6];
    const float* wv     = (const float*)d_in[7];
    const float* bv     = (const float*)d_in[8];
    const float* wo     = (const float*)d_in[9];
    const float* bo     = (const float*)d_in[10];
    const float* ln2_g  = (const float*)d_in[11];
    const float* ln2_b  = (const float*)d_in[12];
    const float* w1     = (const float*)d_in[13];
    const float* b1     = (const float*)d_in[14];
    const float* w2     = (const float*)d_in[15];
    const float* b2     = (const float*)d_in[16];
    const int*   gidx   = (const int*)d_in[17];

    float *q, *k, *v, *h, *ct, *st;
    __nv_bfloat16 *xh, *xl, *ch, *cl, *yh, *yl, *mh, *ml, *wth, *wtl;
    __nv_bfloat16 *qh, *ql, *kh, *kl, *vh;
    cudaGetSymbolAddress((void**)&q,   g_q);
    cudaGetSymbolAddress((void**)&k,   g_k);
    cudaGetSymbolAddress((void**)&v,   g_v);
    cudaGetSymbolAddress((void**)&h,   g_h);
    cudaGetSymbolAddress((void**)&ct,  g_ct);
    cudaGetSymbolAddress((void**)&st,  g_st);
    cudaGetSymbolAddress((void**)&xh,  g_xh);
    cudaGetSymbolAddress((void**)&xl,  g_xl);
    cudaGetSymbolAddress((void**)&ch,  g_ch);
    cudaGetSymbolAddress((void**)&cl,  g_cl);
    cudaGetSymbolAddress((void**)&yh,  g_yh);
    cudaGetSymbolAddress((void**)&yl,  g_yl);
    cudaGetSymbolAddress((void**)&mh,  g_mh);
    cudaGetSymbolAddress((void**)&ml,  g_ml);
    cudaGetSymbolAddress((void**)&wth, g_wth);
    cudaGetSymbolAddress((void**)&wtl, g_wtl);
    cudaGetSymbolAddress((void**)&qh,  g_qh);
    cudaGetSymbolAddress((void**)&ql,  g_ql);
    cudaGetSymbolAddress((void**)&kh,  g_kh);
    cudaGetSymbolAddress((void**)&kl,  g_kl);
    cudaGetSymbolAddress((void**)&vh,  g_vh);

    cudaFuncSetAttribute(gemm_v3<false, false>,
                         cudaFuncAttributeMaxDynamicSharedMemorySize, GEMM_SMEM_BYTES);
    cudaFuncSetAttribute(gemm_v3<true, true>,
                         cudaFuncAttributeMaxDynamicSharedMemorySize, GEMM_SMEM_BYTES);
    cudaFuncSetAttribute(attn_mma,
                         cudaFuncAttributeMaxDynamicSharedMemorySize, ATT_SMEM);

    dim3 wgDmDm(DM / 32, DM / 32);
    dim3 tb32(32, 8);

    // 0. rope tables (cheap; overlaps nothing critical)
    rope_table<<<(S_LEN * 32 + 255) / 256, 256>>>(ct, st);

    // 1. LN1 -> split
    ln_kernel<<<NROWS, 256>>>(hidden, ln1_g, ln1_b, xh, xl);

    // 2. QKV projections (3 separate GEMMs, fp32 out)
    dim3 gqkv(DM / 128, NROWS / 128);
    wsplit_t<<<wgDmDm, tb32>>>(wq, wth, wtl, DM, DM);
    gemm_v3<false, false><<<gqkv, 128, GEMM_SMEM_BYTES>>>(
        xh, xl, wth, wtl, bq, nullptr, q, nullptr, nullptr, NROWS, DM, DM);
    wsplit_t<<<wgDmDm, tb32>>>(wk, wth, wtl, DM, DM);
    gemm_v3<false, false><<<gqkv, 128, GEMM_SMEM_BYTES>>>(
        xh, xl, wth, wtl, bk, nullptr, k, nullptr, nullptr, NROWS, DM, DM);
    wsplit_t<<<wgDmDm, tb32>>>(wv, wth, wtl, DM, DM);
    gemm_v3<false, false><<<gqkv, 128, GEMM_SMEM_BYTES>>>(
        xh, xl, wth, wtl, bv, nullptr, v, nullptr, nullptr, NROWS, DM, DM);

    // 3. Fused table-driven RoPE + split (standalone rope pass eliminated)
    qkv_rope_split<<<NROWS * DM / 4 / 256, 256>>>(q, k, v, ct, st,
                                                  qh, ql, kh, kl, vh);

    // 4. Attention (tensor-core flash, V hi-only) + global-query fixup
    attn_mma<<<dim3(S_LEN / 64, NHEADS, 2), 128, ATT_SMEM>>>(
        qh, ql, kh, kl, vh, ch, cl, gidx);
    attn_global_fix<<<dim3(8, NHEADS, 2), 128>>>(
        qh, ql, kh, kl, v, ch, cl, gidx);

    // 5. O-proj + residual -> h (fp32)
    wsplit_t<<<wgDmDm, tb32>>>(wo, wth, wtl, DM, DM);
    gemm_v3<false, false><<<gqkv, 128, GEMM_SMEM_BYTES>>>(
        ch, cl, wth, wtl, bo, hidden, h, nullptr, nullptr, NROWS, DM, DM);

    // 6. LN2 -> split
    ln_kernel<<<NROWS, 256>>>(h, ln2_g, ln2_b, yh, yl);

    // 7. MLP up + GELU -> mid split
    dim3 gmlp1(DFF / 128, NROWS / 128);
    wsplit_t<<<dim3(DFF / 32, DM / 32), tb32>>>(w1, wth, wtl, DM, DFF);
    gemm_v3<true, true><<<gmlp1, 128, GEMM_SMEM_BYTES>>>(
        yh, yl, wth, wtl, b1, nullptr, nullptr, mh, ml, NROWS, DFF, DM);

    // 8. MLP down + residual -> out
    dim3 gmlp2(DM / 128, NROWS / 128);
    wsplit_t<<<dim3(DM / 32, DFF / 32), tb32>>>(w2, wth, wtl, DFF, DM);
    gemm_v3<false, false><<<gmlp2, 128, GEMM_SMEM_BYTES>>>(
        mh, ml, wth, wtl, b2, h, out, nullptr, nullptr, NROWS, DM, DFF);
}

// round 15
// speedup vs baseline: 1.0208x; 1.0208x over previous
#include <cuda_runtime.h>
#include <cuda_bf16.h>
#include <math.h>
#include <stdint.h>

#define S_LEN 2048
#define DM 1024
#define NHEADS 16
#define DH 64
#define DFF 4096
#define NROWS 4096   // B*S = 2*2048
#define WINDOW 512

#define BP 40        // bf16 smem pitch for GEMM tiles (80B rows)
#define AP 72        // bf16 smem pitch for attention tiles (144B rows)

// ---------------- scratch (static device globals; no allocation) ----------------
__device__ float g_q[NROWS * DM];
__device__ float g_k[NROWS * DM];
__device__ float g_v[NROWS * DM];
__device__ float g_h[NROWS * DM];
__device__ __nv_bfloat16 g_xh[NROWS * DM], g_xl[NROWS * DM];   // LN1 out (split)
__device__ __nv_bfloat16 g_ch[NROWS * DM], g_cl[NROWS * DM];   // ctx (split)
__device__ __nv_bfloat16 g_yh[NROWS * DM], g_yl[NROWS * DM];   // LN2 out (split)
__device__ __nv_bfloat16 g_mh[NROWS * DFF], g_ml[NROWS * DFF]; // mid (split)
__device__ __nv_bfloat16 g_wth[DM * DFF], g_wtl[DM * DFF];     // weight^T (split)
__device__ __nv_bfloat16 g_qh[NROWS * DM], g_ql[NROWS * DM];   // q split (post-RoPE)
__device__ __nv_bfloat16 g_kh[NROWS * DM], g_kl[NROWS * DM];   // k split
__device__ __nv_bfloat16 g_vh[NROWS * DM];                     // v hi only

// =================== helpers ===================
__device__ __forceinline__ uint32_t cvta_shared_u32(const void* p) {
    uint32_t a;
    asm("{ .reg .u64 t; cvta.to.shared.u64 t, %1; cvt.u32.u64 %0, t; }"
        : "=r"(a) : "l"(p));
    return a;
}
__device__ __forceinline__ void ldm_x4(uint32_t addr, uint32_t* r) {
    asm volatile("ldmatrix.sync.aligned.m8n8.x4.shared.b16 {%0,%1,%2,%3}, [%4];"
                 : "=r"(r[0]), "=r"(r[1]), "=r"(r[2]), "=r"(r[3]) : "r"(addr));
}
__device__ __forceinline__ void ldm_x4_t(uint32_t addr, uint32_t* r) {
    asm volatile("ldmatrix.sync.aligned.m8n8.x4.trans.shared.b16 {%0,%1,%2,%3}, [%4];"
                 : "=r"(r[0]), "=r"(r[1]), "=r"(r[2]), "=r"(r[3]) : "r"(addr));
}
__device__ __forceinline__ void mma_bf16(float* c, const uint32_t* a,
                                         uint32_t b0, uint32_t b1) {
    asm volatile(
        "mma.sync.aligned.m16n8k16.row.col.f32.bf16.bf16.f32 "
        "{%0,%1,%2,%3}, {%4,%5,%6,%7}, {%8,%9}, {%0,%1,%2,%3};"
        : "+f"(c[0]), "+f"(c[1]), "+f"(c[2]), "+f"(c[3])
        : "r"(a[0]), "r"(a[1]), "r"(a[2]), "r"(a[3]), "r"(b0), "r"(b1));
}
__device__ __forceinline__ void split_bf16(float x, __nv_bfloat16& h, __nv_bfloat16& l) {
    h = __float2bfloat16(x);
    l = __float2bfloat16(x - __bfloat162float(h));
}
__device__ __forceinline__ uint2 pack4(__nv_bfloat16 a, __nv_bfloat16 b,
                                       __nv_bfloat16 c, __nv_bfloat16 d) {
    __nv_bfloat162 p0 = __halves2bfloat162(a, b);
    __nv_bfloat162 p1 = __halves2bfloat162(c, d);
    uint2 r;
    r.x = *(uint32_t*)&p0;
    r.y = *(uint32_t*)&p1;
    return r;
}
__device__ __forceinline__ uint32_t pack2f(float a, float b) {
    __nv_bfloat162 p = __floats2bfloat162_rn(a, b);
    return *(uint32_t*)&p;
}
__device__ __forceinline__ void cp16(uint32_t saddr, const void* g) {
    asm volatile("cp.async.cg.shared.global [%0], [%1], 16;"
                 :: "r"(saddr), "l"(g));
}

// =================== weight transpose + split: W[K,N] -> Wt[N,K] hi/lo ==========
__global__ void wsplit_t(const float* __restrict__ W,
                         __nv_bfloat16* __restrict__ Th,
                         __nv_bfloat16* __restrict__ Tl, int K, int N)
{
    __shared__ float t[32][33];
    int nb = blockIdx.x * 32, kb = blockIdx.y * 32;
    int tx = threadIdx.x, ty = threadIdx.y;
    #pragma unroll
    for (int r = 0; r < 4; r++)
        t[ty + r * 8][tx] = W[(size_t)(kb + ty + r * 8) * N + nb + tx];
    __syncthreads();
    #pragma unroll
    for (int r = 0; r < 4; r++) {
        int n = nb + ty + r * 8;
        float x = t[tx][ty + r * 8];
        __nv_bfloat16 hh, ll;
        split_bf16(x, hh, ll);
        Th[(size_t)n * K + kb + tx] = hh;
        Tl[(size_t)n * K + kb + tx] = ll;
    }
}

// =================== bf16x3 mma.sync GEMM v4: 128x64 tile, 3 CTAs/SM ============
// BK=32, 128 thr = 4 warps (2M x 2N), warp tile 64x32, 2-stage cp.async.
// stage layout (bytes): Ah 0 (10240), Al 10240, Bh 20480 (5120), Bl 25600;
// stage stride 30720; total 61440.
template<bool GELU, bool SPLIT_OUT>
__global__ void __launch_bounds__(128, 3)
gemm_v4(const __nv_bfloat16* __restrict__ Ah, const __nv_bfloat16* __restrict__ Al,
        const __nv_bfloat16* __restrict__ Bth, const __nv_bfloat16* __restrict__ Btl,
        const float* __restrict__ bias, const float* __restrict__ residual,
        float* __restrict__ C, __nv_bfloat16* __restrict__ Ch,
        __nv_bfloat16* __restrict__ Cl, int M, int N, int K)
{
    extern __shared__ __nv_bfloat16 S[];
    uint32_t smem_u = cvta_shared_u32(S);

    int tid = threadIdx.x, wid = tid >> 5, lane = tid & 31;
    int g = lane >> 2, tg = lane & 3;
    int warpM = wid >> 1, warpN = wid & 1;
    int bm = blockIdx.y * 128, bn = blockIdx.x * 64;
    const int NS = K >> 5;

    float acc[4][4][4];
    #pragma unroll
    for (int mi = 0; mi < 4; mi++)
        #pragma unroll
        for (int ni = 0; ni < 4; ni++)
            #pragma unroll
            for (int r = 0; r < 4; r++) acc[mi][ni][r] = 0.0f;

    auto issue_stage = [&](int s, int b) {
        int k0 = s << 5;
        uint32_t sb = smem_u + b * 30720;
        // A: 128 rows x 32k, 512 16B-chunks per h/l
        #pragma unroll
        for (int u = 0; u < 4; u++) {
            int idx = (u << 7) + tid;
            int r = idx >> 2, c = idx & 3;
            uint32_t soff = (uint32_t)(r * BP + (c << 3)) * 2;
            size_t ga = (size_t)(bm + r) * K + k0 + (c << 3);
            cp16(sb + soff,         Ah + ga);
            cp16(sb + 10240 + soff, Al + ga);
        }
        // B: 64 rows x 32k, 256 chunks per h/l
        #pragma unroll
        for (int u = 0; u < 2; u++) {
            int idx = (u << 7) + tid;
            int r = idx >> 2, c = idx & 3;
            uint32_t soff = (uint32_t)(r * BP + (c << 3)) * 2;
            size_t gb = (size_t)(bn + r) * K + k0 + (c << 3);
            cp16(sb + 20480 + soff, Bth + gb);
            cp16(sb + 25600 + soff, Btl + gb);
        }
    };

    issue_stage(0, 0);
    asm volatile("cp.async.commit_group;" ::: "memory");

    int l8 = lane & 7, qq = lane >> 3;
    int brow_base = warpN * 32 + ((qq >> 1) << 3) + l8;  // + pr*16
    int bcol_base = (qq & 1) << 3;

    for (int s = 0; s < NS; s++) {
        int b = s & 1;
        if (s + 1 < NS) {
            issue_stage(s + 1, b ^ 1);
            asm volatile("cp.async.commit_group;" ::: "memory");
            asm volatile("cp.async.wait_group 1;" ::: "memory");
        } else {
            asm volatile("cp.async.wait_group 0;" ::: "memory");
        }
        __syncthreads();

        uint32_t baseA = smem_u + b * 30720;
        uint32_t baseB = baseA + 20480;

        #pragma unroll
        for (int ks = 0; ks < 2; ks++) {
            uint32_t ah[4][4], al[4][4];
            int rowsel = lane & 15;
            int colsel = (ks << 4) + ((lane >> 4) << 3);
            #pragma unroll
            for (int mi = 0; mi < 4; mi++) {
                int row = (warpM << 6) + (mi << 4) + rowsel;
                uint32_t ad = baseA + (uint32_t)(row * BP + colsel) * 2;
                ldm_x4(ad, ah[mi]);
                ldm_x4(ad + 10240, al[mi]);
            }
            uint32_t bh[4][2], bl[4][2];
            #pragma unroll
            for (int pr = 0; pr < 2; pr++) {
                int row = brow_base + (pr << 4);
                uint32_t ba = baseB + (uint32_t)(row * BP + bcol_base + (ks << 4)) * 2;
                uint32_t t[4];
                ldm_x4(ba, t);
                bh[2*pr][0] = t[0]; bh[2*pr][1] = t[1];
                bh[2*pr+1][0] = t[2]; bh[2*pr+1][1] = t[3];
                ldm_x4(ba + 5120, t);
                bl[2*pr][0] = t[0]; bl[2*pr][1] = t[1];
                bl[2*pr+1][0] = t[2]; bl[2*pr+1][1] = t[3];
            }
            #pragma unroll
            for (int ni = 0; ni < 4; ni++)
                #pragma unroll
                for (int mi = 0; mi < 4; mi++) {
                    mma_bf16(acc[mi][ni], ah[mi], bh[ni][0], bh[ni][1]);
                    mma_bf16(acc[mi][ni], ah[mi], bl[ni][0], bl[ni][1]);
                    mma_bf16(acc[mi][ni], al[mi], bh[ni][0], bh[ni][1]);
                }
        }
        __syncthreads();
    }

    // ---- epilogue ----
    #pragma unroll
    for (int mi = 0; mi < 4; mi++) {
        int r0 = bm + (warpM << 6) + (mi << 4) + g;
        #pragma unroll
        for (int ni = 0; ni < 4; ni++) {
            int c = bn + (warpN << 5) + (ni << 3) + (tg << 1);
            float b0 = bias[c], b1 = bias[c + 1];
            float v00 = acc[mi][ni][0] + b0;
            float v01 = acc[mi][ni][1] + b1;
            float v10 = acc[mi][ni][2] + b0;
            float v11 = acc[mi][ni][3] + b1;
            if (residual) {
                float2 r0v = *(const float2*)&residual[(size_t)r0 * N + c];
                float2 r1v = *(const float2*)&residual[(size_t)(r0 + 8) * N + c];
                v00 += r0v.x; v01 += r0v.y; v10 += r1v.x; v11 += r1v.y;
            }
            if (GELU) {
                v00 = 0.5f * v00 * (1.0f + erff(v00 * 0.70710678118654752f));
                v01 = 0.5f * v01 * (1.0f + erff(v01 * 0.70710678118654752f));
                v10 = 0.5f * v10 * (1.0f + erff(v10 * 0.70710678118654752f));
                v11 = 0.5f * v11 * (1.0f + erff(v11 * 0.70710678118654752f));
            }
            if (SPLIT_OUT) {
                __nv_bfloat16 h0, l0, h1, l1;
                split_bf16(v00, h0, l0); split_bf16(v01, h1, l1);
                *(__nv_bfloat162*)&Ch[(size_t)r0 * N + c] = __halves2bfloat162(h0, h1);
                *(__nv_bfloat162*)&Cl[(size_t)r0 * N + c] = __halves2bfloat162(l0, l1);
                split_bf16(v10, h0, l0); split_bf16(v11, h1, l1);
                *(__nv_bfloat162*)&Ch[(size_t)(r0 + 8) * N + c] = __halves2bfloat162(h0, h1);
                *(__nv_bfloat162*)&Cl[(size_t)(r0 + 8) * N + c] = __halves2bfloat162(l0, l1);
            } else {
                float2 w0 = {v00, v01}, w1 = {v10, v11};
                *(float2*)&C[(size_t)r0 * N + c] = w0;
                *(float2*)&C[(size_t)(r0 + 8) * N + c] = w1;
            }
        }
    }
}

#define GEMM_SMEM_BYTES 61440

// ---------------- LayerNorm -> split bf16 out ----------------
__global__ void ln_kernel(const float* __restrict__ x, const float* __restrict__ g,
                          const float* __restrict__ b,
                          __nv_bfloat16* __restrict__ yh, __nv_bfloat16* __restrict__ yl)
{
    int row = blockIdx.x;
    int tid = threadIdx.x;
    const float4* xr = (const float4*)(x + (size_t)row * DM);
    float4 v = xr[tid];

    __shared__ float rs[256];
    rs[tid] = v.x + v.y + v.z + v.w;
    __syncthreads();
    for (int k = 128; k > 0; k >>= 1) {
        if (tid < k) rs[tid] += rs[tid + k];
        __syncthreads();
    }
    float mean = rs[0] * (1.0f / DM);
    __syncthreads();

    float dx0 = v.x - mean, dx1 = v.y - mean, dx2 = v.z - mean, dx3 = v.w - mean;
    rs[tid] = dx0*dx0 + dx1*dx1 + dx2*dx2 + dx3*dx3;
    __syncthreads();
    for (int k = 128; k > 0; k >>= 1) {
        if (tid < k) rs[tid] += rs[tid + k];
        __syncthreads();
    }
    float var = rs[0] * (1.0f / DM);
    float inv = rsqrtf(var + 1e-5f);

    float4 gg = ((const float4*)g)[tid];
    float4 bb = ((const float4*)b)[tid];
    float o0 = dx0 * inv * gg.x + bb.x;
    float o1 = dx1 * inv * gg.y + bb.y;
    float o2 = dx2 * inv * gg.z + bb.z;
    float o3 = dx3 * inv * gg.w + bb.w;
    __nv_bfloat16 h0, l0, h1, l1, h2, l2, h3, l3;
    split_bf16(o0, h0, l0); split_bf16(o1, h1, l1);
    split_bf16(o2, h2, l2); split_bf16(o3, h3, l3);
    size_t off = (size_t)row * DM + tid * 4;
    *(uint2*)&yh[off] = pack4(h0, h1, h2, h3);
    *(uint2*)&yl[off] = pack4(l0, l1, l2, l3);
}

// ---------------- RoPE (fp32, proven) ----------------
__global__ void rope_kernel(float* __restrict__ q, float* __restrict__ k)
{
    int t = blockIdx.x * blockDim.x + threadIdx.x;
    if (t >= NROWS * NHEADS * 32) return;
    int m = t & 31;
    int rest = t >> 5;
    int h = rest & (NHEADS - 1);
    int n = rest >> 4;
    int s = n & (S_LEN - 1);

    float invf = 1.0f / powf(10000.0f, (float)(2 * m) / 64.0f);
    float ang = (float)s * invf;
    float c = cosf(ang);
    float sn = sinf(ang);

    size_t base = (size_t)n * DM + h * DH + m;
    float x1 = q[base], x2 = q[base + 32];
    q[base]      = x1 * c - x2 * sn;
    q[base + 32] = x2 * c + x1 * sn;
    x1 = k[base]; x2 = k[base + 32];
    k[base]      = x1 * c - x2 * sn;
    k[base + 32] = x2 * c + x1 * sn;
}

// ---------------- q/k/v fp32 -> split bf16 (v: hi only) ----------------
__global__ void qkv_split(const float* __restrict__ q, const float* __restrict__ k,
                          const float* __restrict__ v,
                          __nv_bfloat16* __restrict__ qh, __nv_bfloat16* __restrict__ ql,
                          __nv_bfloat16* __restrict__ kh, __nv_bfloat16* __restrict__ kl,
                          __nv_bfloat16* __restrict__ vh)
{
    size_t t = (size_t)blockIdx.x * 256 + threadIdx.x;
    size_t off = t * 4;
    __nv_bfloat16 h0, l0, h1, l1, h2, l2, h3, l3;
    float4 a = *(const float4*)&q[off];
    split_bf16(a.x, h0, l0); split_bf16(a.y, h1, l1);
    split_bf16(a.z, h2, l2); split_bf16(a.w, h3, l3);
    *(uint2*)&qh[off] = pack4(h0, h1, h2, h3);
    *(uint2*)&ql[off] = pack4(l0, l1, l2, l3);
    a = *(const float4*)&k[off];
    split_bf16(a.x, h0, l0); split_bf16(a.y, h1, l1);
    split_bf16(a.z, h2, l2); split_bf16(a.w, h3, l3);
    *(uint2*)&kh[off] = pack4(h0, h1, h2, h3);
    *(uint2*)&kl[off] = pack4(l0, l1, l2, l3);
    a = *(const float4*)&v[off];
    *(uint2*)&vh[off] = pack4(__float2bfloat16(a.x), __float2bfloat16(a.y),
                              __float2bfloat16(a.z), __float2bfloat16(a.w));
}

// ================= FlashAttention-2 style mma attention (V hi-only) =============
#define ATT_SMEM (5 * 64 * AP * 2)

__global__ void __launch_bounds__(128)
attn_mma(const __nv_bfloat16* __restrict__ qh_g, const __nv_bfloat16* __restrict__ ql_g,
         const __nv_bfloat16* __restrict__ kh_g, const __nv_bfloat16* __restrict__ kl_g,
         const __nv_bfloat16* __restrict__ vh_g,
         __nv_bfloat16* __restrict__ ch, __nv_bfloat16* __restrict__ cl,
         const int* __restrict__ gidx)
{
    extern __shared__ __nv_bfloat16 AS[];
    __nv_bfloat16* Qh = AS;
    __nv_bfloat16* Ql = Qh + 64 * AP;
    __nv_bfloat16* Kh = Ql + 64 * AP;
    __nv_bfloat16* Kl = Kh + 64 * AP;
    __nv_bfloat16* Vh = Kl + 64 * AP;
    __shared__ unsigned char gflag[64];
    __shared__ int glist[8];
    __shared__ int ng_s;

    int q0 = blockIdx.x * 64, h = blockIdx.y, b = blockIdx.z;
    int tid = threadIdx.x, wid = tid >> 5, lane = tid & 31;
    int g = lane >> 2, tg = lane & 3;

    uint32_t qh_u = cvta_shared_u32(Qh);
    uint32_t vh_u = cvta_shared_u32(Vh);

    int g0 = gidx[0], g1 = gidx[1], g2 = gidx[2], g3 = gidx[3];
    int g4 = gidx[4], g5 = gidx[5], g6 = gidx[6], g7 = gidx[7];

    size_t rowbase = ((size_t)(b * S_LEN + q0)) * DM + h * DH;
    for (int u = tid; u < 512; u += 128) {
        int r = u >> 3, c8 = (u & 7) << 3;
        size_t ga = rowbase + (size_t)r * DM + c8;
        *(uint4*)&Qh[r * AP + c8] = *(const uint4*)&qh_g[ga];
        *(uint4*)&Ql[r * AP + c8] = *(const uint4*)&ql_g[ga];
    }

    int lo = q0 - (WINDOW - 1);
    if (lo < 0) lo = 0;
    int jt_start = (lo >> 6) << 6;

    if (tid == 0) {
        int ng = 0;
        int gs[8] = {g0, g1, g2, g3, g4, g5, g6, g7};
        for (int t = 0; t < 8; t++) {
            int j = gs[t];
            if (j < jt_start) {
                bool dup = false;
                for (int u = 0; u < ng; u++) if (glist[u] == j) dup = true;
                if (!dup) glist[ng++] = j;
            }
        }
        ng_s = ng;
    }
    __syncthreads();
    int ng = ng_s;

    uint32_t aqh[4][4], aql[4][4];
    {
        int rowsel = lane & 15;
        int colsel = (lane >> 4) << 3;
        #pragma unroll
        for (int kk = 0; kk < 4; kk++) {
            uint32_t qa = qh_u + (uint32_t)(((wid << 4) + rowsel) * AP + (kk << 4) + colsel) * 2;
            ldm_x4(qa, aqh[kk]);
            ldm_x4(qa + 9216, aql[kk]);
        }
    }

    float m0 = -1e30f, l0 = 0.0f, m1 = -1e30f, l1 = 0.0f;
    float o[8][4];
    #pragma unroll
    for (int ni = 0; ni < 8; ni++)
        #pragma unroll
        for (int r = 0; r < 4; r++) o[ni][r] = 0.0f;

    int i0 = q0 + (wid << 4) + g;
    int i1 = i0 + 8;

    auto process = [&](int jt0, bool extras) {
        float sc[8][4];
        #pragma unroll
        for (int ni = 0; ni < 8; ni++)
            #pragma unroll
            for (int r = 0; r < 4; r++) sc[ni][r] = 0.0f;

        #pragma unroll
        for (int kk = 0; kk < 4; kk++) {
            int koff = (kk << 4) + (tg << 1);
            #pragma unroll
            for (int ni = 0; ni < 8; ni++) {
                int krow = (ni << 3) + g;
                uint32_t bh0 = *(const uint32_t*)&Kh[krow * AP + koff];
                uint32_t bh1 = *(const uint32_t*)&Kh[krow * AP + koff + 8];
                uint32_t bl0 = *(const uint32_t*)&Kl[krow * AP + koff];
                uint32_t bl1 = *(const uint32_t*)&Kl[krow * AP + koff + 8];
                mma_bf16(sc[ni], aqh[kk], bh0, bh1);
                mma_bf16(sc[ni], aql[kk], bh0, bh1);
                mma_bf16(sc[ni], aqh[kk], bl0, bl1);
            }
        }

        #pragma unroll
        for (int ni = 0; ni < 8; ni++) {
            #pragma unroll
            for (int cc = 0; cc < 2; cc++) {
                int jr = (ni << 3) + (tg << 1) + cc;
                bool a0, a1;
                if (extras) {
                    a0 = a1 = (jr < ng);
                } else {
                    int j = jt0 + jr;
                    bool fl = gflag[jr] != 0;
                    a0 = (j <= i0) && (((i0 - j) < WINDOW) || fl);
                    a1 = (j <= i1) && (((i1 - j) < WINDOW) || fl);
                }
                sc[ni][cc]     = a0 ? sc[ni][cc] * 0.125f     : -1e30f;
                sc[ni][2 + cc] = a1 ? sc[ni][2 + cc] * 0.125f : -1e30f;
            }
        }

        float t0 = -1e30f, t1 = -1e30f;
        #pragma unroll
        for (int ni = 0; ni < 8; ni++) {
            t0 = fmaxf(t0, fmaxf(sc[ni][0], sc[ni][1]));
            t1 = fmaxf(t1, fmaxf(sc[ni][2], sc[ni][3]));
        }
        t0 = fmaxf(t0, __shfl_xor_sync(0xffffffffu, t0, 1));
        t0 = fmaxf(t0, __shfl_xor_sync(0xffffffffu, t0, 2));
        t1 = fmaxf(t1, __shfl_xor_sync(0xffffffffu, t1, 1));
        t1 = fmaxf(t1, __shfl_xor_sync(0xffffffffu, t1, 2));
        float nm0 = fmaxf(m0, t0), nm1 = fmaxf(m1, t1);
        float esc0 = __expf(m0 - nm0), esc1 = __expf(m1 - nm1);
        float s0 = 0.0f, s1 = 0.0f;
        #pragma unroll
        for (int ni = 0; ni < 8; ni++) {
            #pragma unroll
            for (int cc = 0; cc < 2; cc++) {
                float p = __expf(sc[ni][cc] - nm0);
                p = __bfloat162float(__float2bfloat16(p));
                sc[ni][cc] = p;
                s0 += p;
                float p2 = __expf(sc[ni][2 + cc] - nm1);
                p2 = __bfloat162float(__float2bfloat16(p2));
                sc[ni][2 + cc] = p2;
                s1 += p2;
            }
        }
        s0 += __shfl_xor_sync(0xffffffffu, s0, 1);
        s0 += __shfl_xor_sync(0xffffffffu, s0, 2);
        s1 += __shfl_xor_sync(0xffffffffu, s1, 1);
        s1 += __shfl_xor_sync(0xffffffffu, s1, 2);
        l0 = l0 * esc0 + s0;
        l1 = l1 * esc1 + s1;
        m0 = nm0; m1 = nm1;
        #pragma unroll
        for (int ni = 0; ni < 8; ni++) {
            o[ni][0] *= esc0; o[ni][1] *= esc0;
            o[ni][2] *= esc1; o[ni][3] *= esc1;
        }

        int vrow = lane & 15;
        int vcol = (lane >> 4) << 3;
        #pragma unroll
        for (int kk = 0; kk < 4; kk++) {
            uint32_t ap[4];
            ap[0] = pack2f(sc[2 * kk][0], sc[2 * kk][1]);
            ap[1] = pack2f(sc[2 * kk][2], sc[2 * kk][3]);
            ap[2] = pack2f(sc[2 * kk + 1][0], sc[2 * kk + 1][1]);
            ap[3] = pack2f(sc[2 * kk + 1][2], sc[2 * kk + 1][3]);
            #pragma unroll
            for (int np = 0; np < 4; np++) {
                uint32_t va = vh_u + (uint32_t)(((kk << 4) + vrow) * AP + (np << 4) + vcol) * 2;
                uint32_t bv[4];
                ldm_x4_t(va, bv);
                mma_bf16(o[2 * np],     ap, bv[0], bv[1]);
                mma_bf16(o[2 * np + 1], ap, bv[2], bv[3]);
            }
        }
    };

    if (ng > 0) {
        for (int u = tid; u < 512; u += 128) {
            int r = u >> 3, c8 = (u & 7) << 3;
            if (r < ng) {
                size_t ga = ((size_t)(b * S_LEN + glist[r])) * DM + h * DH + c8;
                *(uint4*)&Kh[r * AP + c8] = *(const uint4*)&kh_g[ga];
                *(uint4*)&Kl[r * AP + c8] = *(const uint4*)&kl_g[ga];
                *(uint4*)&Vh[r * AP + c8] = *(const uint4*)&vh_g[ga];
            } else {
                uint4 z = {0, 0, 0, 0};
                *(uint4*)&Vh[r * AP + c8] = z;
                *(uint4*)&Kh[r * AP + c8] = z;
                *(uint4*)&Kl[r * AP + c8] = z;
            }
        }
        __syncthreads();
        process(0, true);
        __syncthreads();
    }

    for (int jt0 = jt_start; jt0 <= q0; jt0 += 64) {
        for (int u = tid; u < 512; u += 128) {
            int r = u >> 3, c8 = (u & 7) << 3;
            size_t ga = ((size_t)(b * S_LEN + jt0 + r)) * DM + h * DH + c8;
            *(uint4*)&Kh[r * AP + c8] = *(const uint4*)&kh_g[ga];
            *(uint4*)&Kl[r * AP + c8] = *(const uint4*)&kl_g[ga];
            *(uint4*)&Vh[r * AP + c8] = *(const uint4*)&vh_g[ga];
        }
        if (tid < 64) {
            int j = jt0 + tid;
            gflag[tid] = (j==g0)||(j==g1)||(j==g2)||(j==g3)||(j==g4)||(j==g5)||(j==g6)||(j==g7);
        }
        __syncthreads();
        process(jt0, false);
        __syncthreads();
    }

    float inv0 = 1.0f / l0, inv1 = 1.0f / l1;
    size_t base0 = ((size_t)(b * S_LEN + i0)) * DM + h * DH;
    size_t base1 = base0 + (size_t)8 * DM;
    #pragma unroll
    for (int ni = 0; ni < 8; ni++) {
        int c = (ni << 3) + (tg << 1);
        __nv_bfloat16 h0, lo0, h1, lo1;
        split_bf16(o[ni][0] * inv0, h0, lo0);
        split_bf16(o[ni][1] * inv0, h1, lo1);
        *(__nv_bfloat162*)&ch[base0 + c] = __halves2bfloat162(h0, h1);
        *(__nv_bfloat162*)&cl[base0 + c] = __halves2bfloat162(lo0, lo1);
        split_bf16(o[ni][2] * inv1, h0, lo0);
        split_bf16(o[ni][3] * inv1, h1, lo1);
        *(__nv_bfloat162*)&ch[base1 + c] = __halves2bfloat162(h0, h1);
        *(__nv_bfloat162*)&cl[base1 + c] = __halves2bfloat162(lo0, lo1);
    }
}

// ---------------- fix-up: exact full-causal rows for global queries ----------
__global__ void __launch_bounds__(128)
attn_global_fix(const float* __restrict__ q, const float* __restrict__ k,
                const float* __restrict__ v,
                __nv_bfloat16* __restrict__ ch, __nv_bfloat16* __restrict__ cl,
                const int* __restrict__ gidx)
{
    int i = gidx[blockIdx.x];
    int h = blockIdx.y;
    int b = blockIdx.z;
    int tid = threadIdx.x;

    __shared__ float qs[DH];
    __shared__ float p[S_LEN];
    __shared__ float red[128];
    __shared__ float ctxp[2][DH];

    size_t qbase = ((size_t)(b * S_LEN + i)) * DM + h * DH;
    if (tid < DH) qs[tid] = q[qbase + tid];
    __syncthreads();

    int n = i + 1;

    for (int j = tid; j < n; j += 128) {
        const float* krow = &k[((size_t)(b * S_LEN + j)) * DM + h * DH];
        float d = 0.0f;
        #pragma unroll
        for (int dd = 0; dd < DH; dd++) d += qs[dd] * krow[dd];
        p[j] = d * 0.125f;
    }
    __syncthreads();

    float mx_p = -1e30f;
    for (int j = tid; j < n; j += 128) mx_p = fmaxf(mx_p, p[j]);
    red[tid] = mx_p; __syncthreads();
    for (int s2 = 64; s2 > 0; s2 >>= 1) {
        if (tid < s2) red[tid] = fmaxf(red[tid], red[tid + s2]);
        __syncthreads();
    }
    float mx = red[0];
    __syncthreads();

    float sm = 0.0f;
    for (int j = tid; j < n; j += 128) {
        float e = __expf(p[j] - mx);
        p[j] = e;
        sm += e;
    }
    red[tid] = sm; __syncthreads();
    for (int s2 = 64; s2 > 0; s2 >>= 1) {
        if (tid < s2) red[tid] += red[tid + s2];
        __syncthreads();
    }
    float denom = red[0];

    int half = tid >> 6, d = tid & 63;
    float acc = 0.0f;
    for (int j = half; j < n; j += 2)
        acc += p[j] * v[((size_t)(b * S_LEN + j)) * DM + h * DH + d];
    ctxp[half][d] = acc;
    __syncthreads();
    if (tid < DH) {
        float val = (ctxp[0][tid] + ctxp[1][tid]) / denom;
        __nv_bfloat16 hh, ll;
        split_bf16(val, hh, ll);
        ch[qbase + tid] = hh;
        cl[qbase + tid] = ll;
    }
}

// ---------------- sentinel ----------------
__global__ void sentinel_kernel(float* out, int n)
{
    int t = blockIdx.x * blockDim.x + threadIdx.x;
    if (t < n) out[t] = 1.0e6f;
}

// ---------------- host launcher ----------------
extern "C" void kernel_launch(void* const* d_in, const int* in_sizes, int n_in,
                              void* d_out, int out_size)
{
    float* out = (float*)d_out;

    bool ok = (n_in == 18)
        && (in_sizes[0]  == NROWS * DM)
        && (in_sizes[1]  == DM)
        && (in_sizes[3]  == DM * DM)
        && (in_sizes[13] == DM * DFF)
        && (in_sizes[14] == DFF)
        && (in_sizes[15] == DFF * DM)
        && (in_sizes[16] == DM)
        && (in_sizes[17] == 8);
    if (!ok) {
        sentinel_kernel<<<(out_size + 255) / 256, 256>>>(out, out_size);
        return;
    }

    const float* hidden = (const float*)d_in[0];
    const float* ln1_g  = (const float*)d_in[1];
    const float* ln1_b  = (const float*)d_in[2];
    const float* wq     = (const float*)d_in[3];
    const float* bq     = (const float*)d_in[4];
    const float* wk     = (const float*)d_in[5];
    const float* bk     = (const float*)d_in[6];
    const float* wv     = (const float*)d_in[7];
    const float* bv     = (const float*)d_in[8];
    const float* wo     = (const float*)d_in[9];
    const float* bo     = (const float*)d_in[10];
    const float* ln2_g  = (const float*)d_in[11];
    const float* ln2_b  = (const float*)d_in[12];
    const float* w1     = (const float*)d_in[13];
    const float* b1     = (const float*)d_in[14];
    const float* w2     = (const float*)d_in[15];
    const float* b2     = (const float*)d_in[16];
    const int*   gidx   = (const int*)d_in[17];

    float *q, *k, *v, *h;
    __nv_bfloat16 *xh, *xl, *ch, *cl, *yh, *yl, *mh, *ml, *wth, *wtl;
    __nv_bfloat16 *qh, *ql, *kh, *kl, *vh;
    cudaGetSymbolAddress((void**)&q,   g_q);
    cudaGetSymbolAddress((void**)&k,   g_k);
    cudaGetSymbolAddress((void**)&v,   g_v);
    cudaGetSymbolAddress((void**)&h,   g_h);
    cudaGetSymbolAddress((void**)&xh,  g_xh);
    cudaGetSymbolAddress((void**)&xl,  g_xl);
    cudaGetSymbolAddress((void**)&ch,  g_ch);
    cudaGetSymbolAddress((void**)&cl,  g_cl);
    cudaGetSymbolAddress((void**)&yh,  g_yh);
    cudaGetSymbolAddress((void**)&yl,  g_yl);
    cudaGetSymbolAddress((void**)&mh,  g_mh);
    cudaGetSymbolAddress((void**)&ml,  g_ml);
    cudaGetSymbolAddress((void**)&wth, g_wth);
    cudaGetSymbolAddress((void**)&wtl, g_wtl);
    cudaGetSymbolAddress((void**)&qh,  g_qh);
    cudaGetSymbolAddress((void**)&ql,  g_ql);
    cudaGetSymbolAddress((void**)&kh,  g_kh);
    cudaGetSymbolAddress((void**)&kl,  g_kl);
    cudaGetSymbolAddress((void**)&vh,  g_vh);

    cudaFuncSetAttribute(gemm_v4<false, false>,
                         cudaFuncAttributeMaxDynamicSharedMemorySize, GEMM_SMEM_BYTES);
    cudaFuncSetAttribute(gemm_v4<true, true>,
                         cudaFuncAttributeMaxDynamicSharedMemorySize, GEMM_SMEM_BYTES);
    cudaFuncSetAttribute(attn_mma,
                         cudaFuncAttributeMaxDynamicSharedMemorySize, ATT_SMEM);

    dim3 wgDmDm(DM / 32, DM / 32);
    dim3 tb32(32, 8);

    // 1. LN1 -> split
    ln_kernel<<<NROWS, 256>>>(hidden, ln1_g, ln1_b, xh, xl);

    // 2. QKV projections (3 separate GEMMs, fp32 out; 128x64 tiles)
    dim3 gqkv(DM / 64, NROWS / 128);
    wsplit_t<<<wgDmDm, tb32>>>(wq, wth, wtl, DM, DM);
    gemm_v4<false, false><<<gqkv, 128, GEMM_SMEM_BYTES>>>(
        xh, xl, wth, wtl, bq, nullptr, q, nullptr, nullptr, NROWS, DM, DM);
    wsplit_t<<<wgDmDm, tb32>>>(wk, wth, wtl, DM, DM);
    gemm_v4<false, false><<<gqkv, 128, GEMM_SMEM_BYTES>>>(
        xh, xl, wth, wtl, bk, nullptr, k, nullptr, nullptr, NROWS, DM, DM);
    wsplit_t<<<wgDmDm, tb32>>>(wv, wth, wtl, DM, DM);
    gemm_v4<false, false><<<gqkv, 128, GEMM_SMEM_BYTES>>>(
        xh, xl, wth, wtl, bv, nullptr, v, nullptr, nullptr, NROWS, DM, DM);

    // 3. RoPE (fp32), then split (v: hi only)
    int rope_threads = NROWS * NHEADS * 32;
    rope_kernel<<<(rope_threads + 255) / 256, 256>>>(q, k);
    qkv_split<<<NROWS * DM / 4 / 256, 256>>>(q, k, v, qh, ql, kh, kl, vh);

    // 4. Attention (tensor-core flash, V hi-only) + global-query fixup (exact)
    attn_mma<<<dim3(S_LEN / 64, NHEADS, 2), 128, ATT_SMEM>>>(
        qh, ql, kh, kl, vh, ch, cl, gidx);
    attn_global_fix<<<dim3(8, NHEADS, 2), 128>>>(q, k, v, ch, cl, gidx);

    // 5. O-proj + residual -> h (fp32)
    wsplit_t<<<wgDmDm, tb32>>>(wo, wth, wtl, DM, DM);
    gemm_v4<false, false><<<gqkv, 128, GEMM_SMEM_BYTES>>>(
        ch, cl, wth, wtl, bo, hidden, h, nullptr, nullptr, NROWS, DM, DM);

    // 6. LN2 -> split
    ln_kernel<<<NROWS, 256>>>(h, ln2_g, ln2_b, yh, yl);

    // 7. MLP up + GELU -> mid split
    dim3 gmlp1(DFF / 64, NROWS / 128);
    wsplit_t<<<dim3(DFF / 32, DM / 32), tb32>>>(w1, wth, wtl, DM, DFF);
    gemm_v4<true, true><<<gmlp1, 128, GEMM_SMEM_BYTES>>>(
        yh, yl, wth, wtl, b1, nullptr, nullptr, mh, ml, NROWS, DFF, DM);

    // 8. MLP down + residual -> out
    dim3 gmlp2(DM / 64, NROWS / 128);
    wsplit_t<<<dim3(DM / 32, DFF / 32), tb32>>>(w2, wth, wtl, DFF, DM);
    gemm_v4<false, false><<<gmlp2, 128, GEMM_SMEM_BYTES>>>(
        mh, ml, wth, wtl, b2, h, out, nullptr, nullptr, NROWS, DM, DFF);
}

// round 16
// speedup vs baseline: 1.0811x; 1.0592x over previous
#include <cuda_runtime.h>
#include <cuda_bf16.h>
#include <math.h>
#include <stdint.h>

#define S_LEN 2048
#define DM 1024
#define NHEADS 16
#define DH 64
#define DFF 4096
#define NROWS 4096   // B*S = 2*2048
#define WINDOW 512

#define BP 40        // bf16 smem pitch for GEMM tiles (80B rows)
#define AP 72        // bf16 smem pitch for attention tiles (144B rows)

// ---------------- scratch (static device globals; no allocation) ----------------
__device__ float g_q[NROWS * DM];
__device__ float g_k[NROWS * DM];
__device__ float g_v[NROWS * DM];
__device__ float g_h[NROWS * DM];
__device__ __nv_bfloat16 g_xh[NROWS * DM], g_xl[NROWS * DM];   // LN1 out (split)
__device__ __nv_bfloat16 g_ch[NROWS * DM], g_cl[NROWS * DM];   // ctx (split)
__device__ __nv_bfloat16 g_yh[NROWS * DM], g_yl[NROWS * DM];   // LN2 out (split)
__device__ __nv_bfloat16 g_mh[NROWS * DFF], g_ml[NROWS * DFF]; // mid (split)
// dedicated weight^T (split) buffers, one pair per GEMM (enables overlap)
__device__ __nv_bfloat16 g_wqh[DM * DM],  g_wql[DM * DM];
__device__ __nv_bfloat16 g_wkh[DM * DM],  g_wkl[DM * DM];
__device__ __nv_bfloat16 g_wvh[DM * DM],  g_wvl[DM * DM];
__device__ __nv_bfloat16 g_woh[DM * DM],  g_wol[DM * DM];
__device__ __nv_bfloat16 g_w1h[DM * DFF], g_w1l[DM * DFF];
__device__ __nv_bfloat16 g_w2h[DFF * DM], g_w2l[DFF * DM];
__device__ __nv_bfloat16 g_qh[NROWS * DM], g_ql[NROWS * DM];   // q split (post-RoPE)
__device__ __nv_bfloat16 g_kh[NROWS * DM], g_kl[NROWS * DM];   // k split
__device__ __nv_bfloat16 g_vh[NROWS * DM];                     // v hi only

// =================== helpers ===================
__device__ __forceinline__ uint32_t cvta_shared_u32(const void* p) {
    uint32_t a;
    asm("{ .reg .u64 t; cvta.to.shared.u64 t, %1; cvt.u32.u64 %0, t; }"
        : "=r"(a) : "l"(p));
    return a;
}
__device__ __forceinline__ void ldm_x4(uint32_t addr, uint32_t* r) {
    asm volatile("ldmatrix.sync.aligned.m8n8.x4.shared.b16 {%0,%1,%2,%3}, [%4];"
                 : "=r"(r[0]), "=r"(r[1]), "=r"(r[2]), "=r"(r[3]) : "r"(addr));
}
__device__ __forceinline__ void ldm_x4_t(uint32_t addr, uint32_t* r) {
    asm volatile("ldmatrix.sync.aligned.m8n8.x4.trans.shared.b16 {%0,%1,%2,%3}, [%4];"
                 : "=r"(r[0]), "=r"(r[1]), "=r"(r[2]), "=r"(r[3]) : "r"(addr));
}
__device__ __forceinline__ void mma_bf16(float* c, const uint32_t* a,
                                         uint32_t b0, uint32_t b1) {
    asm volatile(
        "mma.sync.aligned.m16n8k16.row.col.f32.bf16.bf16.f32 "
        "{%0,%1,%2,%3}, {%4,%5,%6,%7}, {%8,%9}, {%0,%1,%2,%3};"
        : "+f"(c[0]), "+f"(c[1]), "+f"(c[2]), "+f"(c[3])
        : "r"(a[0]), "r"(a[1]), "r"(a[2]), "r"(a[3]), "r"(b0), "r"(b1));
}
__device__ __forceinline__ void split_bf16(float x, __nv_bfloat16& h, __nv_bfloat16& l) {
    h = __float2bfloat16(x);
    l = __float2bfloat16(x - __bfloat162float(h));
}
__device__ __forceinline__ uint2 pack4(__nv_bfloat16 a, __nv_bfloat16 b,
                                       __nv_bfloat16 c, __nv_bfloat16 d) {
    __nv_bfloat162 p0 = __halves2bfloat162(a, b);
    __nv_bfloat162 p1 = __halves2bfloat162(c, d);
    uint2 r;
    r.x = *(uint32_t*)&p0;
    r.y = *(uint32_t*)&p1;
    return r;
}
__device__ __forceinline__ uint32_t pack2f(float a, float b) {
    __nv_bfloat162 p = __floats2bfloat162_rn(a, b);
    return *(uint32_t*)&p;
}
__device__ __forceinline__ void cp16(uint32_t saddr, const void* g) {
    asm volatile("cp.async.cg.shared.global [%0], [%1], 16;"
                 :: "r"(saddr), "l"(g));
}

// =================== weight transpose + split: W[K,N] -> Wt[N,K] hi/lo ==========
__global__ void wsplit_t(const float* __restrict__ W,
                         __nv_bfloat16* __restrict__ Th,
                         __nv_bfloat16* __restrict__ Tl, int K, int N)
{
    __shared__ float t[32][33];
    int nb = blockIdx.x * 32, kb = blockIdx.y * 32;
    int tx = threadIdx.x, ty = threadIdx.y;
    #pragma unroll
    for (int r = 0; r < 4; r++)
        t[ty + r * 8][tx] = W[(size_t)(kb + ty + r * 8) * N + nb + tx];
    __syncthreads();
    #pragma unroll
    for (int r = 0; r < 4; r++) {
        int n = nb + ty + r * 8;
        float x = t[tx][ty + r * 8];
        __nv_bfloat16 hh, ll;
        split_bf16(x, hh, ll);
        Th[(size_t)n * K + kb + tx] = hh;
        Tl[(size_t)n * K + kb + tx] = ll;
    }
}

// =================== bf16x3 mma.sync GEMM v3 (R13-proven) ===================
template<bool GELU, bool SPLIT_OUT>
__global__ void __launch_bounds__(128, 2)
gemm_v3(const __nv_bfloat16* __restrict__ Ah, const __nv_bfloat16* __restrict__ Al,
        const __nv_bfloat16* __restrict__ Bth, const __nv_bfloat16* __restrict__ Btl,
        const float* __restrict__ bias, const float* __restrict__ residual,
        float* __restrict__ C, __nv_bfloat16* __restrict__ Ch,
        __nv_bfloat16* __restrict__ Cl, int M, int N, int K)
{
    extern __shared__ __nv_bfloat16 S[];
    uint32_t smem_u = cvta_shared_u32(S);

    int tid = threadIdx.x, wid = tid >> 5, lane = tid & 31;
    int g = lane >> 2, tg = lane & 3;
    int warpM = wid >> 1, warpN = wid & 1;
    int bm = blockIdx.y * 128, bn = blockIdx.x * 128;
    const int NS = K >> 5;

    float acc[4][8][4];
    #pragma unroll
    for (int mi = 0; mi < 4; mi++)
        #pragma unroll
        for (int ni = 0; ni < 8; ni++)
            #pragma unroll
            for (int r = 0; r < 4; r++) acc[mi][ni][r] = 0.0f;

    auto issue_stage = [&](int s, int b) {
        int k0 = s << 5;
        uint32_t sb = smem_u + b * 40960;
        #pragma unroll
        for (int u = 0; u < 4; u++) {
            int idx = (u << 7) + tid;
            int r = idx >> 2, c = idx & 3;
            uint32_t soff = (uint32_t)(r * BP + (c << 3)) * 2;
            size_t ga = (size_t)(bm + r) * K + k0 + (c << 3);
            size_t gb = (size_t)(bn + r) * K + k0 + (c << 3);
            cp16(sb + soff,         Ah + ga);
            cp16(sb + 10240 + soff, Al + ga);
            cp16(sb + 20480 + soff, Bth + gb);
            cp16(sb + 30720 + soff, Btl + gb);
        }
    };

    issue_stage(0, 0);
    asm volatile("cp.async.commit_group;" ::: "memory");

    int l8 = lane & 7, qq = lane >> 3;
    int brow_base = warpN * 64 + ((qq >> 1) << 3) + l8;
    int bcol_base = (qq & 1) << 3;

    for (int s = 0; s < NS; s++) {
        int b = s & 1;
        if (s + 1 < NS) {
            issue_stage(s + 1, b ^ 1);
            asm volatile("cp.async.commit_group;" ::: "memory");
            asm volatile("cp.async.wait_group 1;" ::: "memory");
        } else {
            asm volatile("cp.async.wait_group 0;" ::: "memory");
        }
        __syncthreads();

        uint32_t baseA = smem_u + b * 40960;
        uint32_t baseB = baseA + 20480;

        #pragma unroll
        for (int ks = 0; ks < 2; ks++) {
            uint32_t ah[4][4], al[4][4];
            int rowsel = lane & 15;
            int colsel = (ks << 4) + ((lane >> 4) << 3);
            #pragma unroll
            for (int mi = 0; mi < 4; mi++) {
                int row = (warpM << 6) + (mi << 4) + rowsel;
                uint32_t ad = baseA + (uint32_t)(row * BP + colsel) * 2;
                ldm_x4(ad, ah[mi]);
                ldm_x4(ad + 10240, al[mi]);
            }
            uint32_t bh[8][2], bl[8][2];
            #pragma unroll
            for (int pr = 0; pr < 4; pr++) {
                int row = brow_base + (pr << 4);
                uint32_t ba = baseB + (uint32_t)(row * BP + bcol_base + (ks << 4)) * 2;
                uint32_t t[4];
                ldm_x4(ba, t);
                bh[2*pr][0] = t[0]; bh[2*pr][1] = t[1];
                bh[2*pr+1][0] = t[2]; bh[2*pr+1][1] = t[3];
                ldm_x4(ba + 10240, t);
                bl[2*pr][0] = t[0]; bl[2*pr][1] = t[1];
                bl[2*pr+1][0] = t[2]; bl[2*pr+1][1] = t[3];
            }
            #pragma unroll
            for (int ni = 0; ni < 8; ni++)
                #pragma unroll
                for (int mi = 0; mi < 4; mi++) {
                    mma_bf16(acc[mi][ni], ah[mi], bh[ni][0], bh[ni][1]);
                    mma_bf16(acc[mi][ni], ah[mi], bl[ni][0], bl[ni][1]);
                    mma_bf16(acc[mi][ni], al[mi], bh[ni][0], bh[ni][1]);
                }
        }
        __syncthreads();
    }

    // ---- epilogue ----
    #pragma unroll
    for (int mi = 0; mi < 4; mi++) {
        int r0 = bm + (warpM << 6) + (mi << 4) + g;
        #pragma unroll
        for (int ni = 0; ni < 8; ni++) {
            int c = bn + (warpN << 6) + (ni << 3) + (tg << 1);
            float b0 = bias[c], b1 = bias[c + 1];
            float v00 = acc[mi][ni][0] + b0;
            float v01 = acc[mi][ni][1] + b1;
            float v10 = acc[mi][ni][2] + b0;
            float v11 = acc[mi][ni][3] + b1;
            if (residual) {
                float2 r0v = *(const float2*)&residual[(size_t)r0 * N + c];
                float2 r1v = *(const float2*)&residual[(size_t)(r0 + 8) * N + c];
                v00 += r0v.x; v01 += r0v.y; v10 += r1v.x; v11 += r1v.y;
            }
            if (GELU) {
                v00 = 0.5f * v00 * (1.0f + erff(v00 * 0.70710678118654752f));
                v01 = 0.5f * v01 * (1.0f + erff(v01 * 0.70710678118654752f));
                v10 = 0.5f * v10 * (1.0f + erff(v10 * 0.70710678118654752f));
                v11 = 0.5f * v11 * (1.0f + erff(v11 * 0.70710678118654752f));
            }
            if (SPLIT_OUT) {
                __nv_bfloat16 h0, l0, h1, l1;
                split_bf16(v00, h0, l0); split_bf16(v01, h1, l1);
                *(__nv_bfloat162*)&Ch[(size_t)r0 * N + c] = __halves2bfloat162(h0, h1);
                *(__nv_bfloat162*)&Cl[(size_t)r0 * N + c] = __halves2bfloat162(l0, l1);
                split_bf16(v10, h0, l0); split_bf16(v11, h1, l1);
                *(__nv_bfloat162*)&Ch[(size_t)(r0 + 8) * N + c] = __halves2bfloat162(h0, h1);
                *(__nv_bfloat162*)&Cl[(size_t)(r0 + 8) * N + c] = __halves2bfloat162(l0, l1);
            } else {
                float2 w0 = {v00, v01}, w1 = {v10, v11};
                *(float2*)&C[(size_t)r0 * N + c] = w0;
                *(float2*)&C[(size_t)(r0 + 8) * N + c] = w1;
            }
        }
    }
}

#define GEMM_SMEM_BYTES 81920

// ---------------- LayerNorm -> split bf16 out ----------------
__global__ void ln_kernel(const float* __restrict__ x, const float* __restrict__ g,
                          const float* __restrict__ b,
                          __nv_bfloat16* __restrict__ yh, __nv_bfloat16* __restrict__ yl)
{
    int row = blockIdx.x;
    int tid = threadIdx.x;
    const float4* xr = (const float4*)(x + (size_t)row * DM);
    float4 v = xr[tid];

    __shared__ float rs[256];
    rs[tid] = v.x + v.y + v.z + v.w;
    __syncthreads();
    for (int k = 128; k > 0; k >>= 1) {
        if (tid < k) rs[tid] += rs[tid + k];
        __syncthreads();
    }
    float mean = rs[0] * (1.0f / DM);
    __syncthreads();

    float dx0 = v.x - mean, dx1 = v.y - mean, dx2 = v.z - mean, dx3 = v.w - mean;
    rs[tid] = dx0*dx0 + dx1*dx1 + dx2*dx2 + dx3*dx3;
    __syncthreads();
    for (int k = 128; k > 0; k >>= 1) {
        if (tid < k) rs[tid] += rs[tid + k];
        __syncthreads();
    }
    float var = rs[0] * (1.0f / DM);
    float inv = rsqrtf(var + 1e-5f);

    float4 gg = ((const float4*)g)[tid];
    float4 bb = ((const float4*)b)[tid];
    float o0 = dx0 * inv * gg.x + bb.x;
    float o1 = dx1 * inv * gg.y + bb.y;
    float o2 = dx2 * inv * gg.z + bb.z;
    float o3 = dx3 * inv * gg.w + bb.w;
    __nv_bfloat16 h0, l0, h1, l1, h2, l2, h3, l3;
    split_bf16(o0, h0, l0); split_bf16(o1, h1, l1);
    split_bf16(o2, h2, l2); split_bf16(o3, h3, l3);
    size_t off = (size_t)row * DM + tid * 4;
    *(uint2*)&yh[off] = pack4(h0, h1, h2, h3);
    *(uint2*)&yl[off] = pack4(l0, l1, l2, l3);
}

// ---------------- RoPE (fp32, proven) ----------------
__global__ void rope_kernel(float* __restrict__ q, float* __restrict__ k)
{
    int t = blockIdx.x * blockDim.x + threadIdx.x;
    if (t >= NROWS * NHEADS * 32) return;
    int m = t & 31;
    int rest = t >> 5;
    int h = rest & (NHEADS - 1);
    int n = rest >> 4;
    int s = n & (S_LEN - 1);

    float invf = 1.0f / powf(10000.0f, (float)(2 * m) / 64.0f);
    float ang = (float)s * invf;
    float c = cosf(ang);
    float sn = sinf(ang);

    size_t base = (size_t)n * DM + h * DH + m;
    float x1 = q[base], x2 = q[base + 32];
    q[base]      = x1 * c - x2 * sn;
    q[base + 32] = x2 * c + x1 * sn;
    x1 = k[base]; x2 = k[base + 32];
    k[base]      = x1 * c - x2 * sn;
    k[base + 32] = x2 * c + x1 * sn;
}

// ---------------- q/k/v fp32 -> split bf16 (v: hi only) ----------------
__global__ void qkv_split(const float* __restrict__ q, const float* __restrict__ k,
                          const float* __restrict__ v,
                          __nv_bfloat16* __restrict__ qh, __nv_bfloat16* __restrict__ ql,
                          __nv_bfloat16* __restrict__ kh, __nv_bfloat16* __restrict__ kl,
                          __nv_bfloat16* __restrict__ vh)
{
    size_t t = (size_t)blockIdx.x * 256 + threadIdx.x;
    size_t off = t * 4;
    __nv_bfloat16 h0, l0, h1, l1, h2, l2, h3, l3;
    float4 a = *(const float4*)&q[off];
    split_bf16(a.x, h0, l0); split_bf16(a.y, h1, l1);
    split_bf16(a.z, h2, l2); split_bf16(a.w, h3, l3);
    *(uint2*)&qh[off] = pack4(h0, h1, h2, h3);
    *(uint2*)&ql[off] = pack4(l0, l1, l2, l3);
    a = *(const float4*)&k[off];
    split_bf16(a.x, h0, l0); split_bf16(a.y, h1, l1);
    split_bf16(a.z, h2, l2); split_bf16(a.w, h3, l3);
    *(uint2*)&kh[off] = pack4(h0, h1, h2, h3);
    *(uint2*)&kl[off] = pack4(l0, l1, l2, l3);
    a = *(const float4*)&v[off];
    *(uint2*)&vh[off] = pack4(__float2bfloat16(a.x), __float2bfloat16(a.y),
                              __float2bfloat16(a.z), __float2bfloat16(a.w));
}

// ================= FlashAttention-2 style mma attention (V hi-only) =============
#define ATT_SMEM (5 * 64 * AP * 2)

__global__ void __launch_bounds__(128)
attn_mma(const __nv_bfloat16* __restrict__ qh_g, const __nv_bfloat16* __restrict__ ql_g,
         const __nv_bfloat16* __restrict__ kh_g, const __nv_bfloat16* __restrict__ kl_g,
         const __nv_bfloat16* __restrict__ vh_g,
         __nv_bfloat16* __restrict__ ch, __nv_bfloat16* __restrict__ cl,
         const int* __restrict__ gidx)
{
    extern __shared__ __nv_bfloat16 AS[];
    __nv_bfloat16* Qh = AS;
    __nv_bfloat16* Ql = Qh + 64 * AP;
    __nv_bfloat16* Kh = Ql + 64 * AP;
    __nv_bfloat16* Kl = Kh + 64 * AP;
    __nv_bfloat16* Vh = Kl + 64 * AP;
    __shared__ unsigned char gflag[64];
    __shared__ int glist[8];
    __shared__ int ng_s;

    int q0 = blockIdx.x * 64, h = blockIdx.y, b = blockIdx.z;
    int tid = threadIdx.x, wid = tid >> 5, lane = tid & 31;
    int g = lane >> 2, tg = lane & 3;

    uint32_t qh_u = cvta_shared_u32(Qh);
    uint32_t vh_u = cvta_shared_u32(Vh);

    int g0 = gidx[0], g1 = gidx[1], g2 = gidx[2], g3 = gidx[3];
    int g4 = gidx[4], g5 = gidx[5], g6 = gidx[6], g7 = gidx[7];

    size_t rowbase = ((size_t)(b * S_LEN + q0)) * DM + h * DH;
    for (int u = tid; u < 512; u += 128) {
        int r = u >> 3, c8 = (u & 7) << 3;
        size_t ga = rowbase + (size_t)r * DM + c8;
        *(uint4*)&Qh[r * AP + c8] = *(const uint4*)&qh_g[ga];
        *(uint4*)&Ql[r * AP + c8] = *(const uint4*)&ql_g[ga];
    }

    int lo = q0 - (WINDOW - 1);
    if (lo < 0) lo = 0;
    int jt_start = (lo >> 6) << 6;

    if (tid == 0) {
        int ng = 0;
        int gs[8] = {g0, g1, g2, g3, g4, g5, g6, g7};
        for (int t = 0; t < 8; t++) {
            int j = gs[t];
            if (j < jt_start) {
                bool dup = false;
                for (int u = 0; u < ng; u++) if (glist[u] == j) dup = true;
                if (!dup) glist[ng++] = j;
            }
        }
        ng_s = ng;
    }
    __syncthreads();
    int ng = ng_s;

    uint32_t aqh[4][4], aql[4][4];
    {
        int rowsel = lane & 15;
        int colsel = (lane >> 4) << 3;
        #pragma unroll
        for (int kk = 0; kk < 4; kk++) {
            uint32_t qa = qh_u + (uint32_t)(((wid << 4) + rowsel) * AP + (kk << 4) + colsel) * 2;
            ldm_x4(qa, aqh[kk]);
            ldm_x4(qa + 9216, aql[kk]);
        }
    }

    float m0 = -1e30f, l0 = 0.0f, m1 = -1e30f, l1 = 0.0f;
    float o[8][4];
    #pragma unroll
    for (int ni = 0; ni < 8; ni++)
        #pragma unroll
        for (int r = 0; r < 4; r++) o[ni][r] = 0.0f;

    int i0 = q0 + (wid << 4) + g;
    int i1 = i0 + 8;

    auto process = [&](int jt0, bool extras) {
        float sc[8][4];
        #pragma unroll
        for (int ni = 0; ni < 8; ni++)
            #pragma unroll
            for (int r = 0; r < 4; r++) sc[ni][r] = 0.0f;

        #pragma unroll
        for (int kk = 0; kk < 4; kk++) {
            int koff = (kk << 4) + (tg << 1);
            #pragma unroll
            for (int ni = 0; ni < 8; ni++) {
                int krow = (ni << 3) + g;
                uint32_t bh0 = *(const uint32_t*)&Kh[krow * AP + koff];
                uint32_t bh1 = *(const uint32_t*)&Kh[krow * AP + koff + 8];
                uint32_t bl0 = *(const uint32_t*)&Kl[krow * AP + koff];
                uint32_t bl1 = *(const uint32_t*)&Kl[krow * AP + koff + 8];
                mma_bf16(sc[ni], aqh[kk], bh0, bh1);
                mma_bf16(sc[ni], aql[kk], bh0, bh1);
                mma_bf16(sc[ni], aqh[kk], bl0, bl1);
            }
        }

        #pragma unroll
        for (int ni = 0; ni < 8; ni++) {
            #pragma unroll
            for (int cc = 0; cc < 2; cc++) {
                int jr = (ni << 3) + (tg << 1) + cc;
                bool a0, a1;
                if (extras) {
                    a0 = a1 = (jr < ng);
                } else {
                    int j = jt0 + jr;
                    bool fl = gflag[jr] != 0;
                    a0 = (j <= i0) && (((i0 - j) < WINDOW) || fl);
                    a1 = (j <= i1) && (((i1 - j) < WINDOW) || fl);
                }
                sc[ni][cc]     = a0 ? sc[ni][cc] * 0.125f     : -1e30f;
                sc[ni][2 + cc] = a1 ? sc[ni][2 + cc] * 0.125f : -1e30f;
            }
        }

        float t0 = -1e30f, t1 = -1e30f;
        #pragma unroll
        for (int ni = 0; ni < 8; ni++) {
            t0 = fmaxf(t0, fmaxf(sc[ni][0], sc[ni][1]));
            t1 = fmaxf(t1, fmaxf(sc[ni][2], sc[ni][3]));
        }
        t0 = fmaxf(t0, __shfl_xor_sync(0xffffffffu, t0, 1));
        t0 = fmaxf(t0, __shfl_xor_sync(0xffffffffu, t0, 2));
        t1 = fmaxf(t1, __shfl_xor_sync(0xffffffffu, t1, 1));
        t1 = fmaxf(t1, __shfl_xor_sync(0xffffffffu, t1, 2));
        float nm0 = fmaxf(m0, t0), nm1 = fmaxf(m1, t1);
        float esc0 = __expf(m0 - nm0), esc1 = __expf(m1 - nm1);
        float s0 = 0.0f, s1 = 0.0f;
        #pragma unroll
        for (int ni = 0; ni < 8; ni++) {
            #pragma unroll
            for (int cc = 0; cc < 2; cc++) {
                float p = __expf(sc[ni][cc] - nm0);
                p = __bfloat162float(__float2bfloat16(p));
                sc[ni][cc] = p;
                s0 += p;
                float p2 = __expf(sc[ni][2 + cc] - nm1);
                p2 = __bfloat162float(__float2bfloat16(p2));
                sc[ni][2 + cc] = p2;
                s1 += p2;
            }
        }
        s0 += __shfl_xor_sync(0xffffffffu, s0, 1);
        s0 += __shfl_xor_sync(0xffffffffu, s0, 2);
        s1 += __shfl_xor_sync(0xffffffffu, s1, 1);
        s1 += __shfl_xor_sync(0xffffffffu, s1, 2);
        l0 = l0 * esc0 + s0;
        l1 = l1 * esc1 + s1;
        m0 = nm0; m1 = nm1;
        #pragma unroll
        for (int ni = 0; ni < 8; ni++) {
            o[ni][0] *= esc0; o[ni][1] *= esc0;
            o[ni][2] *= esc1; o[ni][3] *= esc1;
        }

        int vrow = lane & 15;
        int vcol = (lane >> 4) << 3;
        #pragma unroll
        for (int kk = 0; kk < 4; kk++) {
            uint32_t ap[4];
            ap[0] = pack2f(sc[2 * kk][0], sc[2 * kk][1]);
            ap[1] = pack2f(sc[2 * kk][2], sc[2 * kk][3]);
            ap[2] = pack2f(sc[2 * kk + 1][0], sc[2 * kk + 1][1]);
            ap[3] = pack2f(sc[2 * kk + 1][2], sc[2 * kk + 1][3]);
            #pragma unroll
            for (int np = 0; np < 4; np++) {
                uint32_t va = vh_u + (uint32_t)(((kk << 4) + vrow) * AP + (np << 4) + vcol) * 2;
                uint32_t bv[4];
                ldm_x4_t(va, bv);
                mma_bf16(o[2 * np],     ap, bv[0], bv[1]);
                mma_bf16(o[2 * np + 1], ap, bv[2], bv[3]);
            }
        }
    };

    if (ng > 0) {
        for (int u = tid; u < 512; u += 128) {
            int r = u >> 3, c8 = (u & 7) << 3;
            if (r < ng) {
                size_t ga = ((size_t)(b * S_LEN + glist[r])) * DM + h * DH + c8;
                *(uint4*)&Kh[r * AP + c8] = *(const uint4*)&kh_g[ga];
                *(uint4*)&Kl[r * AP + c8] = *(const uint4*)&kl_g[ga];
                *(uint4*)&Vh[r * AP + c8] = *(const uint4*)&vh_g[ga];
            } else {
                uint4 z = {0, 0, 0, 0};
                *(uint4*)&Vh[r * AP + c8] = z;
                *(uint4*)&Kh[r * AP + c8] = z;
                *(uint4*)&Kl[r * AP + c8] = z;
            }
        }
        __syncthreads();
        process(0, true);
        __syncthreads();
    }

    for (int jt0 = jt_start; jt0 <= q0; jt0 += 64) {
        for (int u = tid; u < 512; u += 128) {
            int r = u >> 3, c8 = (u & 7) << 3;
            size_t ga = ((size_t)(b * S_LEN + jt0 + r)) * DM + h * DH + c8;
            *(uint4*)&Kh[r * AP + c8] = *(const uint4*)&kh_g[ga];
            *(uint4*)&Kl[r * AP + c8] = *(const uint4*)&kl_g[ga];
            *(uint4*)&Vh[r * AP + c8] = *(const uint4*)&vh_g[ga];
        }
        if (tid < 64) {
            int j = jt0 + tid;
            gflag[tid] = (j==g0)||(j==g1)||(j==g2)||(j==g3)||(j==g4)||(j==g5)||(j==g6)||(j==g7);
        }
        __syncthreads();
        process(jt0, false);
        __syncthreads();
    }

    float inv0 = 1.0f / l0, inv1 = 1.0f / l1;
    size_t base0 = ((size_t)(b * S_LEN + i0)) * DM + h * DH;
    size_t base1 = base0 + (size_t)8 * DM;
    #pragma unroll
    for (int ni = 0; ni < 8; ni++) {
        int c = (ni << 3) + (tg << 1);
        __nv_bfloat16 h0, lo0, h1, lo1;
        split_bf16(o[ni][0] * inv0, h0, lo0);
        split_bf16(o[ni][1] * inv0, h1, lo1);
        *(__nv_bfloat162*)&ch[base0 + c] = __halves2bfloat162(h0, h1);
        *(__nv_bfloat162*)&cl[base0 + c] = __halves2bfloat162(lo0, lo1);
        split_bf16(o[ni][2] * inv1, h0, lo0);
        split_bf16(o[ni][3] * inv1, h1, lo1);
        *(__nv_bfloat162*)&ch[base1 + c] = __halves2bfloat162(h0, h1);
        *(__nv_bfloat162*)&cl[base1 + c] = __halves2bfloat162(lo0, lo1);
    }
}

// ---------------- fix-up: exact full-causal rows for global queries ----------
__global__ void __launch_bounds__(128)
attn_global_fix(const float* __restrict__ q, const float* __restrict__ k,
                const float* __restrict__ v,
                __nv_bfloat16* __restrict__ ch, __nv_bfloat16* __restrict__ cl,
                const int* __restrict__ gidx)
{
    int i = gidx[blockIdx.x];
    int h = blockIdx.y;
    int b = blockIdx.z;
    int tid = threadIdx.x;

    __shared__ float qs[DH];
    __shared__ float p[S_LEN];
    __shared__ float red[128];
    __shared__ float ctxp[2][DH];

    size_t qbase = ((size_t)(b * S_LEN + i)) * DM + h * DH;
    if (tid < DH) qs[tid] = q[qbase + tid];
    __syncthreads();

    int n = i + 1;

    for (int j = tid; j < n; j += 128) {
        const float* krow = &k[((size_t)(b * S_LEN + j)) * DM + h * DH];
        float d = 0.0f;
        #pragma unroll
        for (int dd = 0; dd < DH; dd++) d += qs[dd] * krow[dd];
        p[j] = d * 0.125f;
    }
    __syncthreads();

    float mx_p = -1e30f;
    for (int j = tid; j < n; j += 128) mx_p = fmaxf(mx_p, p[j]);
    red[tid] = mx_p; __syncthreads();
    for (int s2 = 64; s2 > 0; s2 >>= 1) {
        if (tid < s2) red[tid] = fmaxf(red[tid], red[tid + s2]);
        __syncthreads();
    }
    float mx = red[0];
    __syncthreads();

    float sm = 0.0f;
    for (int j = tid; j < n; j += 128) {
        float e = __expf(p[j] - mx);
        p[j] = e;
        sm += e;
    }
    red[tid] = sm; __syncthreads();
    for (int s2 = 64; s2 > 0; s2 >>= 1) {
        if (tid < s2) red[tid] += red[tid + s2];
        __syncthreads();
    }
    float denom = red[0];

    int half = tid >> 6, d = tid & 63;
    float acc = 0.0f;
    for (int j = half; j < n; j += 2)
        acc += p[j] * v[((size_t)(b * S_LEN + j)) * DM + h * DH + d];
    ctxp[half][d] = acc;
    __syncthreads();
    if (tid < DH) {
        float val = (ctxp[0][tid] + ctxp[1][tid]) / denom;
        __nv_bfloat16 hh, ll;
        split_bf16(val, hh, ll);
        ch[qbase + tid] = hh;
        cl[qbase + tid] = ll;
    }
}

// ---------------- sentinel ----------------
__global__ void sentinel_kernel(float* out, int n)
{
    int t = blockIdx.x * blockDim.x + threadIdx.x;
    if (t < n) out[t] = 1.0e6f;
}

// ---------------- host launcher ----------------
extern "C" void kernel_launch(void* const* d_in, const int* in_sizes, int n_in,
                              void* d_out, int out_size)
{
    float* out = (float*)d_out;

    bool ok = (n_in == 18)
        && (in_sizes[0]  == NROWS * DM)
        && (in_sizes[1]  == DM)
        && (in_sizes[3]  == DM * DM)
        && (in_sizes[13] == DM * DFF)
        && (in_sizes[14] == DFF)
        && (in_sizes[15] == DFF * DM)
        && (in_sizes[16] == DM)
        && (in_sizes[17] == 8);
    if (!ok) {
        sentinel_kernel<<<(out_size + 255) / 256, 256>>>(out, out_size);
        return;
    }

    const float* hidden = (const float*)d_in[0];
    const float* ln1_g  = (const float*)d_in[1];
    const float* ln1_b  = (const float*)d_in[2];
    const float* wq     = (const float*)d_in[3];
    const float* bq     = (const float*)d_in[4];
    const float* wk     = (const float*)d_in[5];
    const float* bk     = (const float*)d_in[6];
    const float* wv     = (const float*)d_in[7];
    const float* bv     = (const float*)d_in[8];
    const float* wo     = (const float*)d_in[9];
    const float* bo     = (const float*)d_in[10];
    const float* ln2_g  = (const float*)d_in[11];
    const float* ln2_b  = (const float*)d_in[12];
    const float* w1     = (const float*)d_in[13];
    const float* b1     = (const float*)d_in[14];
    const float* w2     = (const float*)d_in[15];
    const float* b2     = (const float*)d_in[16];
    const int*   gidx   = (const int*)d_in[17];

    float *q, *k, *v, *h;
    __nv_bfloat16 *xh, *xl, *ch, *cl, *yh, *yl, *mh, *ml;
    __nv_bfloat16 *wqh, *wql, *wkh, *wkl, *wvh, *wvl, *woh, *wol;
    __nv_bfloat16 *w1h, *w1l, *w2h, *w2l;
    __nv_bfloat16 *qh, *ql, *kh, *kl, *vh;
    cudaGetSymbolAddress((void**)&q,   g_q);
    cudaGetSymbolAddress((void**)&k,   g_k);
    cudaGetSymbolAddress((void**)&v,   g_v);
    cudaGetSymbolAddress((void**)&h,   g_h);
    cudaGetSymbolAddress((void**)&xh,  g_xh);
    cudaGetSymbolAddress((void**)&xl,  g_xl);
    cudaGetSymbolAddress((void**)&ch,  g_ch);
    cudaGetSymbolAddress((void**)&cl,  g_cl);
    cudaGetSymbolAddress((void**)&yh,  g_yh);
    cudaGetSymbolAddress((void**)&yl,  g_yl);
    cudaGetSymbolAddress((void**)&mh,  g_mh);
    cudaGetSymbolAddress((void**)&ml,  g_ml);
    cudaGetSymbolAddress((void**)&wqh, g_wqh);
    cudaGetSymbolAddress((void**)&wql, g_wql);
    cudaGetSymbolAddress((void**)&wkh, g_wkh);
    cudaGetSymbolAddress((void**)&wkl, g_wkl);
    cudaGetSymbolAddress((void**)&wvh, g_wvh);
    cudaGetSymbolAddress((void**)&wvl, g_wvl);
    cudaGetSymbolAddress((void**)&woh, g_woh);
    cudaGetSymbolAddress((void**)&wol, g_wol);
    cudaGetSymbolAddress((void**)&w1h, g_w1h);
    cudaGetSymbolAddress((void**)&w1l, g_w1l);
    cudaGetSymbolAddress((void**)&w2h, g_w2h);
    cudaGetSymbolAddress((void**)&w2l, g_w2l);
    cudaGetSymbolAddress((void**)&qh,  g_qh);
    cudaGetSymbolAddress((void**)&ql,  g_ql);
    cudaGetSymbolAddress((void**)&kh,  g_kh);
    cudaGetSymbolAddress((void**)&kl,  g_kl);
    cudaGetSymbolAddress((void**)&vh,  g_vh);

    cudaFuncSetAttribute(gemm_v3<false, false>,
                         cudaFuncAttributeMaxDynamicSharedMemorySize, GEMM_SMEM_BYTES);
    cudaFuncSetAttribute(gemm_v3<true, true>,
                         cudaFuncAttributeMaxDynamicSharedMemorySize, GEMM_SMEM_BYTES);
    cudaFuncSetAttribute(attn_mma,
                         cudaFuncAttributeMaxDynamicSharedMemorySize, ATT_SMEM);

    dim3 wgDmDm(DM / 32, DM / 32);
    dim3 tb32(32, 8);

    // ---- side stream for weight prep (graph-capture via event fork/join) ----
    cudaStream_t side;
    cudaStreamCreateWithFlags(&side, cudaStreamNonBlocking);
    cudaEvent_t evFork, evQ, evK, evV, evO, ev1, ev2;
    cudaEventCreateWithFlags(&evFork, cudaEventDisableTiming);
    cudaEventCreateWithFlags(&evQ, cudaEventDisableTiming);
    cudaEventCreateWithFlags(&evK, cudaEventDisableTiming);
    cudaEventCreateWithFlags(&evV, cudaEventDisableTiming);
    cudaEventCreateWithFlags(&evO, cudaEventDisableTiming);
    cudaEventCreateWithFlags(&ev1, cudaEventDisableTiming);
    cudaEventCreateWithFlags(&ev2, cudaEventDisableTiming);

    cudaEventRecord(evFork, 0);
    cudaStreamWaitEvent(side, evFork, 0);

    // weight splits on side stream (depend only on inputs)
    wsplit_t<<<wgDmDm, tb32, 0, side>>>(wq, wqh, wql, DM, DM);
    cudaEventRecord(evQ, side);
    wsplit_t<<<wgDmDm, tb32, 0, side>>>(wk, wkh, wkl, DM, DM);
    cudaEventRecord(evK, side);
    wsplit_t<<<wgDmDm, tb32, 0, side>>>(wv, wvh, wvl, DM, DM);
    cudaEventRecord(evV, side);
    wsplit_t<<<wgDmDm, tb32, 0, side>>>(wo, woh, wol, DM, DM);
    cudaEventRecord(evO, side);
    wsplit_t<<<dim3(DFF / 32, DM / 32), tb32, 0, side>>>(w1, w1h, w1l, DM, DFF);
    cudaEventRecord(ev1, side);
    wsplit_t<<<dim3(DM / 32, DFF / 32), tb32, 0, side>>>(w2, w2h, w2l, DFF, DM);
    cudaEventRecord(ev2, side);

    // ---- main stream ----
    // 1. LN1 -> split
    ln_kernel<<<NROWS, 256>>>(hidden, ln1_g, ln1_b, xh, xl);

    // 2. QKV projections
    dim3 gqkv(DM / 128, NROWS / 128);
    cudaStreamWaitEvent(0, evQ, 0);
    gemm_v3<false, false><<<gqkv, 128, GEMM_SMEM_BYTES>>>(
        xh, xl, wqh, wql, bq, nullptr, q, nullptr, nullptr, NROWS, DM, DM);
    cudaStreamWaitEvent(0, evK, 0);
    gemm_v3<false, false><<<gqkv, 128, GEMM_SMEM_BYTES>>>(
        xh, xl, wkh, wkl, bk, nullptr, k, nullptr, nullptr, NROWS, DM, DM);
    cudaStreamWaitEvent(0, evV, 0);
    gemm_v3<false, false><<<gqkv, 128, GEMM_SMEM_BYTES>>>(
        xh, xl, wvh, wvl, bv, nullptr, v, nullptr, nullptr, NROWS, DM, DM);

    // 3. RoPE (fp32), then split (v: hi only)
    int rope_threads = NROWS * NHEADS * 32;
    rope_kernel<<<(rope_threads + 255) / 256, 256>>>(q, k);
    qkv_split<<<NROWS * DM / 4 / 256, 256>>>(q, k, v, qh, ql, kh, kl, vh);

    // 4. Attention (tensor-core flash, V hi-only) + global-query fixup (exact)
    attn_mma<<<dim3(S_LEN / 64, NHEADS, 2), 128, ATT_SMEM>>>(
        qh, ql, kh, kl, vh, ch, cl, gidx);
    attn_global_fix<<<dim3(8, NHEADS, 2), 128>>>(q, k, v, ch, cl, gidx);

    // 5. O-proj + residual -> h (fp32)
    cudaStreamWaitEvent(0, evO, 0);
    gemm_v3<false, false><<<gqkv, 128, GEMM_SMEM_BYTES>>>(
        ch, cl, woh, wol, bo, hidden, h, nullptr, nullptr, NROWS, DM, DM);

    // 6. LN2 -> split
    ln_kernel<<<NROWS, 256>>>(h, ln2_g, ln2_b, yh, yl);

    // 7. MLP up + GELU -> mid split
    dim3 gmlp1(DFF / 128, NROWS / 128);
    cudaStreamWaitEvent(0, ev1, 0);
    gemm_v3<true, true><<<gmlp1, 128, GEMM_SMEM_BYTES>>>(
        yh, yl, w1h, w1l, b1, nullptr, nullptr, mh, ml, NROWS, DFF, DM);

    // 8. MLP down + residual -> out
    dim3 gmlp2(DM / 128, NROWS / 128);
    cudaStreamWaitEvent(0, ev2, 0);
    gemm_v3<false, false><<<gmlp2, 128, GEMM_SMEM_BYTES>>>(
        mh, ml, w2h, w2l, b2, h, out, nullptr, nullptr, NROWS, DM, DFF);
}